// round 1
// baseline (speedup 1.0000x reference)
#include <cuda_runtime.h>
#include <cuda_bf16.h>
#include <cstdint>

#define O_N   50000
#define T_N   200000
#define DIN   128
#define HID   512
#define DOUT  128

// ---------------- device scratch (allocation-free rule: __device__ globals) ----
__device__ float g_curt[(size_t)T_N * 3 * DIN];   // 307 MB  gathered input  [T, 384]
__device__ float g_h   [(size_t)T_N * HID];       // 410 MB  hidden1         [T, 512]
__device__ float g_pool[(size_t)O_N * HID];       // 102 MB  pooled          [O, 512]
__device__ float g_h2  [(size_t)O_N * HID];       // 102 MB  hidden2         [O, 512]
__device__ float g_cnt [O_N];                     // counts

// ---------------- vectorized global reduction --------------------------------
__device__ __forceinline__ void red_add4(float* p, float4 v) {
    asm volatile("red.global.add.v4.f32 [%0], {%1,%2,%3,%4};"
                 :: "l"(p), "f"(v.x), "f"(v.y), "f"(v.z), "f"(v.w) : "memory");
}

// ---------------- gather: build cur_t = [obj[s], pred, obj[o]] ----------------
__global__ void gather_kernel(const float4* __restrict__ obj,
                              const float4* __restrict__ pred,
                              const int*    __restrict__ edges,
                              float4*       __restrict__ curt,
                              int total /* T_N*96 */) {
    int i = blockIdx.x * 256 + threadIdx.x;
    if (i >= total) return;
    int r = i / 96;
    int j = i - r * 96;               // float4 index within the 384-wide row
    float4 v;
    if (j < 32)       v = obj[(size_t)edges[2*r]     * 32 + j];
    else if (j < 64)  v = pred[(size_t)r             * 32 + (j - 32)];
    else              v = obj[(size_t)edges[2*r + 1] * 32 + (j - 64)];
    curt[i] = v;
}

// ---------------- degree counts ----------------------------------------------
__global__ void counts_kernel(const int* __restrict__ edges, float* __restrict__ cnt) {
    int t = blockIdx.x * 256 + threadIdx.x;
    if (t >= T_N) return;
    atomicAdd(&cnt[edges[2*t    ]], 1.0f);
    atomicAdd(&cnt[edges[2*t + 1]], 1.0f);
}

// ---------------- pooled /= clip(counts,1,O) ---------------------------------
__global__ void pooled_scale_kernel(float4* __restrict__ pooled,
                                    const float* __restrict__ cnt,
                                    int total /* O_N*HID/4 */) {
    int i = blockIdx.x * 256 + threadIdx.x;
    if (i >= total) return;
    int r = i >> 7;                   // / (HID/4 = 128)
    float c = cnt[r];
    c = fminf(fmaxf(c, 1.0f), 50000.0f);
    float s = 1.0f / c;
    float4 v = pooled[i];
    v.x *= s; v.y *= s; v.z *= s; v.w *= s;
    pooled[i] = v;
}

// ---------------- tiled FP32 GEMM with fused relu / scatter epilogue ----------
// C[M,N] = relu(A[M,K] @ B[K,N] + bias)
// EPI==0 : plain store to C
// EPI==1 : GEMM2 routing. N==1152 tiles: n0<512 -> red.add pooled[s_idx];
//          n0==512 tile -> store new_p; n0>=640 -> red.add pooled[o_idx].
#define BM 128
#define BN 128
#define BK 16

template<int EPI>
__global__ void __launch_bounds__(256)
sgemm_kernel(const float* __restrict__ A, const float* __restrict__ B,
             const float* __restrict__ bias, float* __restrict__ C,
             int M, int N, int K,
             const int* __restrict__ edges,
             float* __restrict__ pooled, float* __restrict__ newp)
{
    __shared__ float As[BK][BM];
    __shared__ float Bs[BK][BN];

    const int tid = threadIdx.x;
    const int m0  = blockIdx.x * BM;
    const int n0  = blockIdx.y * BN;
    const int tr  = tid >> 4;     // 0..15
    const int tc  = tid & 15;     // 0..15

    float acc[8][8];
    #pragma unroll
    for (int i = 0; i < 8; i++)
        #pragma unroll
        for (int j = 0; j < 8; j++) acc[i][j] = 0.0f;

    for (int k0 = 0; k0 < K; k0 += BK) {
        // --- load A tile (BM x BK) transposed into As; 512 float4, 2/thread ---
        #pragma unroll
        for (int t = 0; t < 2; t++) {
            int l   = tid + t * 256;
            int row = l >> 2;
            int c4  = l & 3;
            int gr  = m0 + row;
            float4 v = make_float4(0.f, 0.f, 0.f, 0.f);
            if (gr < M) v = *(const float4*)&A[(size_t)gr * K + k0 + c4 * 4];
            As[c4*4 + 0][row] = v.x;
            As[c4*4 + 1][row] = v.y;
            As[c4*4 + 2][row] = v.z;
            As[c4*4 + 3][row] = v.w;
        }
        // --- load B tile (BK x BN); 512 float4, 2/thread ----------------------
        #pragma unroll
        for (int t = 0; t < 2; t++) {
            int l   = tid + t * 256;
            int row = l >> 5;
            int c4  = l & 31;
            float4 v = *(const float4*)&B[(size_t)(k0 + row) * N + n0 + c4 * 4];
            *(float4*)&Bs[row][c4 * 4] = v;
        }
        __syncthreads();

        #pragma unroll
        for (int kk = 0; kk < BK; kk++) {
            float a[8], b[8];
            *(float4*)&a[0] = *(const float4*)&As[kk][tr*8];
            *(float4*)&a[4] = *(const float4*)&As[kk][tr*8 + 4];
            *(float4*)&b[0] = *(const float4*)&Bs[kk][tc*8];
            *(float4*)&b[4] = *(const float4*)&Bs[kk][tc*8 + 4];
            #pragma unroll
            for (int i = 0; i < 8; i++)
                #pragma unroll
                for (int j = 0; j < 8; j++)
                    acc[i][j] = fmaf(a[i], b[j], acc[i][j]);
        }
        __syncthreads();
    }

    float bn[8];
    #pragma unroll
    for (int j = 0; j < 8; j++) bn[j] = bias[n0 + tc*8 + j];

    if (EPI == 0) {
        #pragma unroll
        for (int i = 0; i < 8; i++) {
            int gr = m0 + tr*8 + i;
            if (gr >= M) continue;
            #pragma unroll
            for (int jv = 0; jv < 8; jv += 4) {
                float4 v;
                v.x = fmaxf(acc[i][jv+0] + bn[jv+0], 0.f);
                v.y = fmaxf(acc[i][jv+1] + bn[jv+1], 0.f);
                v.z = fmaxf(acc[i][jv+2] + bn[jv+2], 0.f);
                v.w = fmaxf(acc[i][jv+3] + bn[jv+3], 0.f);
                *(float4*)&C[(size_t)gr * N + n0 + tc*8 + jv] = v;
            }
        }
    } else {
        const int region = (n0 < HID) ? 0 : ((n0 < HID + DOUT) ? 1 : 2);
        #pragma unroll
        for (int i = 0; i < 8; i++) {
            int gr = m0 + tr*8 + i;
            if (gr >= M) continue;
            float v[8];
            #pragma unroll
            for (int j = 0; j < 8; j++) v[j] = fmaxf(acc[i][j] + bn[j], 0.f);
            float4 lo = make_float4(v[0], v[1], v[2], v[3]);
            float4 hi = make_float4(v[4], v[5], v[6], v[7]);
            if (region == 1) {
                int col = n0 - HID + tc*8;
                *(float4*)&newp[(size_t)gr * DOUT + col]     = lo;
                *(float4*)&newp[(size_t)gr * DOUT + col + 4] = hi;
            } else {
                int obj = edges[2*gr + (region >> 1)];   // region 0 -> s, 2 -> o
                int col = (region == 0) ? (n0 + tc*8) : (n0 - (HID + DOUT) + tc*8);
                red_add4(&pooled[(size_t)obj * HID + col],     lo);
                red_add4(&pooled[(size_t)obj * HID + col + 4], hi);
            }
        }
    }
}

// ---------------- launch ------------------------------------------------------
extern "C" void kernel_launch(void* const* d_in, const int* in_sizes, int n_in,
                              void* d_out, int out_size) {
    const float* obj  = (const float*)d_in[0];
    const float* pred = (const float*)d_in[1];
    const int*   edges= (const int*)  d_in[2];
    const float* W1a  = (const float*)d_in[3];
    const float* b1a  = (const float*)d_in[4];
    const float* W1b  = (const float*)d_in[5];
    const float* b1b  = (const float*)d_in[6];
    const float* W2a  = (const float*)d_in[7];
    const float* b2a  = (const float*)d_in[8];
    const float* W2b  = (const float*)d_in[9];
    const float* b2b  = (const float*)d_in[10];

    float* out     = (float*)d_out;
    float* new_obj = out;                               // [O, 128]
    float* new_p   = out + (size_t)O_N * DOUT;          // [T, 128]

    float *curt, *h, *pooled, *h2, *cnt;
    cudaGetSymbolAddress((void**)&curt,   g_curt);
    cudaGetSymbolAddress((void**)&h,      g_h);
    cudaGetSymbolAddress((void**)&pooled, g_pool);
    cudaGetSymbolAddress((void**)&h2,     g_h2);
    cudaGetSymbolAddress((void**)&cnt,    g_cnt);

    cudaMemsetAsync(pooled, 0, (size_t)O_N * HID * sizeof(float));
    cudaMemsetAsync(cnt,    0, (size_t)O_N * sizeof(float));

    {   // gather cur_t
        int total = T_N * 96;
        gather_kernel<<<(total + 255) / 256, 256>>>(
            (const float4*)obj, (const float4*)pred, edges, (float4*)curt, total);
    }
    counts_kernel<<<(T_N + 255) / 256, 256>>>(edges, cnt);

    {   // GEMM1: h = relu(cur_t @ W1a + b1a)   [200000 x 512]
        dim3 g((T_N + BM - 1) / BM, HID / BN);
        sgemm_kernel<0><<<g, 256>>>(curt, W1a, b1a, h, T_N, HID, 3 * DIN,
                                    nullptr, nullptr, nullptr);
    }
    {   // GEMM2 fused: new_t = relu(h @ W1b + b1b) -> scatter/store
        dim3 g((T_N + BM - 1) / BM, (2 * HID + DOUT) / BN);
        sgemm_kernel<1><<<g, 256>>>(h, W1b, b1b, nullptr, T_N, 2 * HID + DOUT, HID,
                                    edges, pooled, new_p);
    }
    {   // pooled /= clip(counts, 1, O)
        int total = O_N * HID / 4;
        pooled_scale_kernel<<<(total + 255) / 256, 256>>>((float4*)pooled, cnt, total);
    }
    {   // GEMM3: h2 = relu(pooled @ W2a + b2a)  [50000 x 512]
        dim3 g((O_N + BM - 1) / BM, HID / BN);
        sgemm_kernel<0><<<g, 256>>>(pooled, W2a, b2a, h2, O_N, HID, HID,
                                    nullptr, nullptr, nullptr);
    }
    {   // GEMM4: new_obj = relu(h2 @ W2b + b2b) [50000 x 128]
        dim3 g((O_N + BM - 1) / BM, DOUT / BN);
        sgemm_kernel<0><<<g, 256>>>(h2, W2b, b2b, new_obj, O_N, DOUT, HID,
                                    nullptr, nullptr, nullptr);
    }
}

// round 3
// speedup vs baseline: 2.2499x; 2.2499x over previous
#include <cuda_runtime.h>
#include <cuda_bf16.h>
#include <cstdint>

#define O_N   50000
#define T_N   200000
#define DIN   128
#define HID   512
#define DOUT  128

// ---------------- device scratch (allocation-free rule) -----------------------
__device__ __nv_bfloat16 g_curt[(size_t)T_N * 768];    // [T, 2*384]  hi|lo
__device__ __nv_bfloat16 g_h   [(size_t)T_N * 1024];   // [T, 2*512]  hi|lo
__device__ float         g_pool[(size_t)O_N * HID];    // fp32 accum
__device__ __nv_bfloat16 g_pool2[(size_t)O_N * 1024];  // [O, 2*512]  hi|lo
__device__ __nv_bfloat16 g_h2  [(size_t)O_N * 1024];   // [O, 2*512]  hi|lo
__device__ float         g_cnt [O_N];
__device__ __nv_bfloat16 g_bt1[(size_t)512  * 1152];   // [N,3K] = [Bhi;Bhi;Blo]
__device__ __nv_bfloat16 g_bt2[(size_t)1152 * 1536];
__device__ __nv_bfloat16 g_bt3[(size_t)512  * 1536];
__device__ __nv_bfloat16 g_bt4[(size_t)128  * 1536];

// ---------------- PTX helpers -------------------------------------------------
__device__ __forceinline__ uint32_t smem_u32(const void* p) {
    uint32_t a;
    asm("{ .reg .u64 t; cvta.to.shared.u64 t, %1; cvt.u32.u64 %0, t; }" : "=r"(a) : "l"(p));
    return a;
}
__device__ __forceinline__ void cp_async16(uint32_t dst, const void* src, int sz) {
    asm volatile("cp.async.cg.shared.global [%0], [%1], 16, %2;"
                 :: "r"(dst), "l"(src), "r"(sz));
}
__device__ __forceinline__ void ldm_x4(uint32_t& r0, uint32_t& r1, uint32_t& r2,
                                       uint32_t& r3, uint32_t addr) {
    asm volatile("ldmatrix.sync.aligned.m8n8.x4.shared.b16 {%0,%1,%2,%3}, [%4];"
                 : "=r"(r0), "=r"(r1), "=r"(r2), "=r"(r3) : "r"(addr));
}
__device__ __forceinline__ void mma_bf16(float* c, const uint32_t* a, const uint32_t* b) {
    asm volatile("mma.sync.aligned.m16n8k16.row.col.f32.bf16.bf16.f32 "
                 "{%0,%1,%2,%3}, {%4,%5,%6,%7}, {%8,%9}, {%0,%1,%2,%3};"
                 : "+f"(c[0]), "+f"(c[1]), "+f"(c[2]), "+f"(c[3])
                 : "r"(a[0]), "r"(a[1]), "r"(a[2]), "r"(a[3]), "r"(b[0]), "r"(b[1]));
}
__device__ __forceinline__ void red_add2(float* p, float a, float b) {
    asm volatile("red.global.add.v2.f32 [%0], {%1,%2};"
                 :: "l"(p), "f"(a), "f"(b) : "memory");
}

// ---------------- feeders -----------------------------------------------------
__global__ void gather_conv(const float4* __restrict__ obj, const float4* __restrict__ pred,
                            const int* __restrict__ edges, __nv_bfloat16* __restrict__ curt) {
    int i = blockIdx.x * 256 + threadIdx.x;
    if (i >= T_N * 96) return;
    int r = i / 96, j = i - r * 96;
    float4 v;
    if (j < 32)       v = obj[(size_t)edges[2*r]     * 32 + j];
    else if (j < 64)  v = pred[(size_t)r             * 32 + (j - 32)];
    else              v = obj[(size_t)edges[2*r + 1] * 32 + (j - 64)];
    __nv_bfloat16 hx = __float2bfloat16(v.x), hy = __float2bfloat16(v.y);
    __nv_bfloat16 hz = __float2bfloat16(v.z), hw = __float2bfloat16(v.w);
    __nv_bfloat16 lx = __float2bfloat16(v.x - __bfloat162float(hx));
    __nv_bfloat16 ly = __float2bfloat16(v.y - __bfloat162float(hy));
    __nv_bfloat16 lz = __float2bfloat16(v.z - __bfloat162float(hz));
    __nv_bfloat16 lw = __float2bfloat16(v.w - __bfloat162float(hw));
    __nv_bfloat16* row = curt + (size_t)r * 768;
    int c = j * 4;
    *(__nv_bfloat162*)(row + c)           = __halves2bfloat162(hx, hy);
    *(__nv_bfloat162*)(row + c + 2)       = __halves2bfloat162(hz, hw);
    *(__nv_bfloat162*)(row + 384 + c)     = __halves2bfloat162(lx, ly);
    *(__nv_bfloat162*)(row + 384 + c + 2) = __halves2bfloat162(lz, lw);
}

// Bt[n, c], c in [0,3K): [Bhi ; Bhi ; Blo] (weights transposed to N-major)
__global__ void wprep(const float* __restrict__ W, __nv_bfloat16* __restrict__ Bt,
                      int K, int N, int Kc) {
    size_t idx = (size_t)blockIdx.x * 256 + threadIdx.x;
    if (idx >= (size_t)N * Kc) return;
    int n = (int)(idx / Kc), c = (int)(idx % Kc);
    int k = (c < K) ? c : ((c < 2 * K) ? c - K : c - 2 * K);
    float w = W[(size_t)k * N + n];
    __nv_bfloat16 h = __float2bfloat16(w);
    Bt[idx] = (c < 2 * K) ? h : __float2bfloat16(w - __bfloat162float(h));
}

__global__ void counts_kernel(const int* __restrict__ edges, float* __restrict__ cnt) {
    int t = blockIdx.x * 256 + threadIdx.x;
    if (t >= T_N) return;
    atomicAdd(&cnt[edges[2*t]], 1.0f);
    atomicAdd(&cnt[edges[2*t + 1]], 1.0f);
}

__global__ void pscale_conv(const float4* __restrict__ pooled, const float* __restrict__ cnt,
                            __nv_bfloat16* __restrict__ p2) {
    int i = blockIdx.x * 256 + threadIdx.x;
    if (i >= O_N * (HID / 4)) return;
    int r = i >> 7;
    float c = fminf(fmaxf(cnt[r], 1.0f), 50000.0f);
    float s = 1.0f / c;
    float4 v = pooled[i];
    v.x *= s; v.y *= s; v.z *= s; v.w *= s;
    __nv_bfloat16 hx = __float2bfloat16(v.x), hy = __float2bfloat16(v.y);
    __nv_bfloat16 hz = __float2bfloat16(v.z), hw = __float2bfloat16(v.w);
    __nv_bfloat16 lx = __float2bfloat16(v.x - __bfloat162float(hx));
    __nv_bfloat16 ly = __float2bfloat16(v.y - __bfloat162float(hy));
    __nv_bfloat16 lz = __float2bfloat16(v.z - __bfloat162float(hz));
    __nv_bfloat16 lw = __float2bfloat16(v.w - __bfloat162float(hw));
    __nv_bfloat16* row = p2 + (size_t)r * 1024;
    int c0 = (i & 127) * 4;
    *(__nv_bfloat162*)(row + c0)           = __halves2bfloat162(hx, hy);
    *(__nv_bfloat162*)(row + c0 + 2)       = __halves2bfloat162(hz, hw);
    *(__nv_bfloat162*)(row + 512 + c0)     = __halves2bfloat162(lx, ly);
    *(__nv_bfloat162*)(row + 512 + c0 + 2) = __halves2bfloat162(lz, lw);
}

// ---------------- mma.sync bf16-split GEMM ------------------------------------
// C tile [128,128] at (m0 = by*128, n0 = bx*128).
// Effective K' = Kc (hi/lo remap: A col = kp<twoK ? kp : kp-twoK).
// EPI 0: fp32 store to outf[row*ostride + col]
// EPI 1: hi/lo bf16 store into outh[row*2*K2 + col] / +K2
// EPI 2: GEMM2 router (col<512 -> s-scatter, 512..639 -> newp, >=640 -> o-scatter)
#define BM 128
#define BN 128
#define BK 32

template<int EPI>
__global__ void __launch_bounds__(256, 2)
mma_gemm(const __nv_bfloat16* __restrict__ A, const __nv_bfloat16* __restrict__ Bt,
         const float* __restrict__ bias, float* __restrict__ outf,
         __nv_bfloat16* __restrict__ outh,
         int M, int twoK, int strideA, int Kc, int ostride, int K2,
         const int* __restrict__ edges, float* __restrict__ pooled,
         float* __restrict__ newp)
{
    __shared__ __nv_bfloat16 As[2][BM * BK];
    __shared__ __nv_bfloat16 Bs[2][BN * BK];

    const int tid  = threadIdx.x;
    const int wid  = tid >> 5;
    const int lane = tid & 31;
    const int m0   = blockIdx.y * BM;
    const int n0   = blockIdx.x * BN;
    const int wm   = (wid >> 2) * 64;   // warp M offset
    const int wn   = (wid & 3) * 32;    // warp N offset

    float acc[4][4][4];
    #pragma unroll
    for (int i = 0; i < 4; i++)
        #pragma unroll
        for (int j = 0; j < 4; j++)
            #pragma unroll
            for (int k = 0; k < 4; k++) acc[i][j][k] = 0.f;

    auto ld_tile = [&](int it, int buf) {
        const int kp = it * BK;
        const int ac = (kp < twoK) ? kp : kp - twoK;
        uint32_t sa  = smem_u32(&As[buf][0]);
        uint32_t sbm = smem_u32(&Bs[buf][0]);
        #pragma unroll
        for (int t = 0; t < 2; t++) {                 // A: 128 rows x 4 chunks(16B)
            int s = tid + t * 256;
            int row = s >> 2, ch = s & 3;
            uint32_t phys = row * 64 + ((ch ^ ((row >> 1) & 3)) << 4);
            int gr = m0 + row;
            cp_async16(sa + phys,
                       A + (size_t)(gr < M ? gr : 0) * strideA + ac + ch * 8,
                       gr < M ? 16 : 0);
        }
        #pragma unroll
        for (int t = 0; t < 2; t++) {                 // B: Bt rows n0..n0+127
            int s = tid + t * 256;
            int row = s >> 2, ch = s & 3;
            uint32_t phys = row * 64 + ((ch ^ ((row >> 1) & 3)) << 4);
            cp_async16(sbm + phys, Bt + (size_t)(n0 + row) * Kc + kp + ch * 8, 16);
        }
        asm volatile("cp.async.commit_group;" ::: "memory");
    };

    const int NC = Kc / BK;
    ld_tile(0, 0);
    for (int it = 0; it < NC; it++) {
        const int buf = it & 1;
        if (it + 1 < NC) {
            ld_tile(it + 1, buf ^ 1);
            asm volatile("cp.async.wait_group 1;" ::: "memory");
        } else {
            asm volatile("cp.async.wait_group 0;" ::: "memory");
        }
        __syncthreads();

        const uint32_t sa = smem_u32(&As[buf][0]);
        const uint32_t sb = smem_u32(&Bs[buf][0]);
        #pragma unroll
        for (int ks = 0; ks < 2; ks++) {
            uint32_t a[4][4], b[4][2];
            #pragma unroll
            for (int mf = 0; mf < 4; mf++) {
                int row = wm + mf * 16 + (lane & 15);
                int ch  = ks * 2 + (lane >> 4);
                uint32_t addr = sa + row * 64 + ((ch ^ ((row >> 1) & 3)) << 4);
                ldm_x4(a[mf][0], a[mf][1], a[mf][2], a[mf][3], addr);
            }
            #pragma unroll
            for (int bi = 0; bi < 2; bi++) {
                int row = wn + bi * 16 + (lane & 15);
                int ch  = ks * 2 + (lane >> 4);
                uint32_t addr = sb + row * 64 + ((ch ^ ((row >> 1) & 3)) << 4);
                uint32_t r0, r1, r2, r3;
                ldm_x4(r0, r1, r2, r3, addr);
                b[bi*2+0][0] = r0; b[bi*2+0][1] = r2;   // n 0-7 of this n16
                b[bi*2+1][0] = r1; b[bi*2+1][1] = r3;   // n 8-15
            }
            #pragma unroll
            for (int mf = 0; mf < 4; mf++)
                #pragma unroll
                for (int nf = 0; nf < 4; nf++)
                    mma_bf16(acc[mf][nf], a[mf], b[nf]);
        }
        __syncthreads();
    }

    // ---------------- epilogue ------------------------------------------------
    #pragma unroll
    for (int mf = 0; mf < 4; mf++) {
        #pragma unroll
        for (int rh = 0; rh < 2; rh++) {
            const int gr = m0 + wm + mf * 16 + (lane >> 2) + rh * 8;
            if (gr >= M) continue;
            int es = 0, eo = 0;
            if (EPI == 2) { es = edges[2*gr]; eo = edges[2*gr + 1]; }
            #pragma unroll
            for (int nf = 0; nf < 4; nf++) {
                const int col = n0 + wn + nf * 8 + (lane & 3) * 2;
                float v0 = fmaxf(acc[mf][nf][rh*2+0] + __ldg(&bias[col]),     0.f);
                float v1 = fmaxf(acc[mf][nf][rh*2+1] + __ldg(&bias[col + 1]), 0.f);
                if (EPI == 0) {
                    float2 v = make_float2(v0, v1);
                    *(float2*)&outf[(size_t)gr * ostride + col] = v;
                } else if (EPI == 1) {
                    __nv_bfloat16 h0 = __float2bfloat16(v0), h1 = __float2bfloat16(v1);
                    __nv_bfloat16 l0 = __float2bfloat16(v0 - __bfloat162float(h0));
                    __nv_bfloat16 l1 = __float2bfloat16(v1 - __bfloat162float(h1));
                    __nv_bfloat16* p = outh + (size_t)gr * (2 * K2) + col;
                    *(__nv_bfloat162*)p        = __halves2bfloat162(h0, h1);
                    *(__nv_bfloat162*)(p + K2) = __halves2bfloat162(l0, l1);
                } else {
                    if (col < HID) {
                        red_add2(&pooled[(size_t)es * HID + col], v0, v1);
                    } else if (col < HID + DOUT) {
                        float2 v = make_float2(v0, v1);
                        *(float2*)&newp[(size_t)gr * DOUT + (col - HID)] = v;
                    } else {
                        red_add2(&pooled[(size_t)eo * HID + (col - HID - DOUT)], v0, v1);
                    }
                }
            }
        }
    }
}

// ---------------- launch ------------------------------------------------------
extern "C" void kernel_launch(void* const* d_in, const int* in_sizes, int n_in,
                              void* d_out, int out_size) {
    const float* obj  = (const float*)d_in[0];
    const float* pred = (const float*)d_in[1];
    const int*   edges= (const int*)  d_in[2];
    const float* W1a  = (const float*)d_in[3];
    const float* b1a  = (const float*)d_in[4];
    const float* W1b  = (const float*)d_in[5];
    const float* b1b  = (const float*)d_in[6];
    const float* W2a  = (const float*)d_in[7];
    const float* b2a  = (const float*)d_in[8];
    const float* W2b  = (const float*)d_in[9];
    const float* b2b  = (const float*)d_in[10];

    float* out     = (float*)d_out;
    float* new_obj = out;                       // [O, 128]
    float* new_p   = out + (size_t)O_N * DOUT;  // [T, 128]

    __nv_bfloat16 *curt, *h2K, *p2, *h2, *bt1, *bt2, *bt3, *bt4;
    float *pooled, *cnt;
    cudaGetSymbolAddress((void**)&curt,   g_curt);
    cudaGetSymbolAddress((void**)&h2K,    g_h);
    cudaGetSymbolAddress((void**)&pooled, g_pool);
    cudaGetSymbolAddress((void**)&p2,     g_pool2);
    cudaGetSymbolAddress((void**)&h2,     g_h2);
    cudaGetSymbolAddress((void**)&cnt,    g_cnt);
    cudaGetSymbolAddress((void**)&bt1,    g_bt1);
    cudaGetSymbolAddress((void**)&bt2,    g_bt2);
    cudaGetSymbolAddress((void**)&bt3,    g_bt3);
    cudaGetSymbolAddress((void**)&bt4,    g_bt4);

    cudaMemsetAsync(pooled, 0, (size_t)O_N * HID * sizeof(float));
    cudaMemsetAsync(cnt,    0, (size_t)O_N * sizeof(float));

    {   size_t n = (size_t)512 * 1152;
        wprep<<<(unsigned)((n + 255) / 256), 256>>>(W1a, bt1, 384, 512, 1152); }
    {   size_t n = (size_t)1152 * 1536;
        wprep<<<(unsigned)((n + 255) / 256), 256>>>(W1b, bt2, 512, 1152, 1536); }
    {   size_t n = (size_t)512 * 1536;
        wprep<<<(unsigned)((n + 255) / 256), 256>>>(W2a, bt3, 512, 512, 1536); }
    {   size_t n = (size_t)128 * 1536;
        wprep<<<(unsigned)((n + 255) / 256), 256>>>(W2b, bt4, 512, 128, 1536); }

    gather_conv<<<(T_N * 96 + 255) / 256, 256>>>(
        (const float4*)obj, (const float4*)pred, edges, curt);
    counts_kernel<<<(T_N + 255) / 256, 256>>>(edges, cnt);

    const int MT_T = (T_N + 127) / 128;   // 1563
    const int MT_O = (O_N + 127) / 128;   // 391

    // GEMM1: h = relu(curt @ W1a + b1a) -> hi/lo bf16   (grid x=N tiles for L2 A reuse)
    mma_gemm<1><<<dim3(4, MT_T), 256>>>(
        curt, bt1, b1a, nullptr, h2K,
        T_N, 768, 768, 1152, 0, HID, nullptr, nullptr, nullptr);

    // GEMM2: new_t = relu(h @ W1b + b1b) -> scatter s/o + store new_p (one launch)
    mma_gemm<2><<<dim3(9, MT_T), 256>>>(
        h2K, bt2, b1b, nullptr, nullptr,
        T_N, 1024, 1024, 1536, 0, 0, edges, pooled, new_p);

    pscale_conv<<<(O_N * (HID / 4) + 255) / 256, 256>>>((const float4*)pooled, cnt, p2);

    // GEMM3: h2 = relu(pooled @ W2a + b2a) -> hi/lo bf16
    mma_gemm<1><<<dim3(4, MT_O), 256>>>(
        p2, bt3, b2a, nullptr, h2,
        O_N, 1024, 1024, 1536, 0, HID, nullptr, nullptr, nullptr);

    // GEMM4: new_obj = relu(h2 @ W2b + b2b)
    mma_gemm<0><<<dim3(1, MT_O), 256>>>(
        h2, bt4, b2b, new_obj, nullptr,
        O_N, 1024, 1024, 1536, DOUT, 0, nullptr, nullptr, nullptr);
}

// round 4
// speedup vs baseline: 2.2656x; 1.0070x over previous
#include <cuda_runtime.h>
#include <cuda_bf16.h>
#include <cstdint>

#define O_N   50000
#define T_N   200000
#define DIN   128
#define HID   512
#define DOUT  128

// ---------------- device scratch (allocation-free rule) -----------------------
__device__ __nv_bfloat16 g_curt[(size_t)T_N * 768];    // [T, 2*384]  hi|lo
__device__ __nv_bfloat16 g_h   [(size_t)T_N * 1024];   // [T, 2*512]  hi|lo
__device__ float         g_pool[(size_t)O_N * HID];    // fp32 accum
__device__ __nv_bfloat16 g_pool2[(size_t)O_N * 1024];  // [O, 2*512]  hi|lo
__device__ __nv_bfloat16 g_h2  [(size_t)O_N * 1024];   // [O, 2*512]  hi|lo
__device__ float         g_cnt [O_N];
__device__ __nv_bfloat16 g_bt1[(size_t)512  * 1152];   // [N,3K] = [Bhi;Bhi;Blo]
__device__ __nv_bfloat16 g_bt2[(size_t)1152 * 1536];
__device__ __nv_bfloat16 g_bt3[(size_t)512  * 1536];
__device__ __nv_bfloat16 g_bt4[(size_t)128  * 1536];

// ---------------- PTX helpers -------------------------------------------------
__device__ __forceinline__ uint32_t smem_u32(const void* p) {
    uint32_t a;
    asm("{ .reg .u64 t; cvta.to.shared.u64 t, %1; cvt.u32.u64 %0, t; }" : "=r"(a) : "l"(p));
    return a;
}
__device__ __forceinline__ void cp_async16(uint32_t dst, const void* src, int sz) {
    asm volatile("cp.async.cg.shared.global [%0], [%1], 16, %2;"
                 :: "r"(dst), "l"(src), "r"(sz));
}
__device__ __forceinline__ void ldm_x4(uint32_t& r0, uint32_t& r1, uint32_t& r2,
                                       uint32_t& r3, uint32_t addr) {
    asm volatile("ldmatrix.sync.aligned.m8n8.x4.shared.b16 {%0,%1,%2,%3}, [%4];"
                 : "=r"(r0), "=r"(r1), "=r"(r2), "=r"(r3) : "r"(addr));
}
__device__ __forceinline__ void mma_bf16(float* c, const uint32_t* a, const uint32_t* b) {
    asm volatile("mma.sync.aligned.m16n8k16.row.col.f32.bf16.bf16.f32 "
                 "{%0,%1,%2,%3}, {%4,%5,%6,%7}, {%8,%9}, {%0,%1,%2,%3};"
                 : "+f"(c[0]), "+f"(c[1]), "+f"(c[2]), "+f"(c[3])
                 : "r"(a[0]), "r"(a[1]), "r"(a[2]), "r"(a[3]), "r"(b[0]), "r"(b[1]));
}
__device__ __forceinline__ void red_add2(float* p, float a, float b) {
    asm volatile("red.global.add.v2.f32 [%0], {%1,%2};"
                 :: "l"(p), "f"(a), "f"(b) : "memory");
}

// ---------------- feeders -----------------------------------------------------
__global__ void gather_conv(const float4* __restrict__ obj, const float4* __restrict__ pred,
                            const int* __restrict__ edges, __nv_bfloat16* __restrict__ curt) {
    int i = blockIdx.x * 256 + threadIdx.x;
    if (i >= T_N * 96) return;
    int r = i / 96, j = i - r * 96;
    float4 v;
    if (j < 32)       v = obj[(size_t)edges[2*r]     * 32 + j];
    else if (j < 64)  v = pred[(size_t)r             * 32 + (j - 32)];
    else              v = obj[(size_t)edges[2*r + 1] * 32 + (j - 64)];
    __nv_bfloat16 hx = __float2bfloat16(v.x), hy = __float2bfloat16(v.y);
    __nv_bfloat16 hz = __float2bfloat16(v.z), hw = __float2bfloat16(v.w);
    __nv_bfloat16 lx = __float2bfloat16(v.x - __bfloat162float(hx));
    __nv_bfloat16 ly = __float2bfloat16(v.y - __bfloat162float(hy));
    __nv_bfloat16 lz = __float2bfloat16(v.z - __bfloat162float(hz));
    __nv_bfloat16 lw = __float2bfloat16(v.w - __bfloat162float(hw));
    __nv_bfloat16* row = curt + (size_t)r * 768;
    int c = j * 4;
    *(__nv_bfloat162*)(row + c)           = __halves2bfloat162(hx, hy);
    *(__nv_bfloat162*)(row + c + 2)       = __halves2bfloat162(hz, hw);
    *(__nv_bfloat162*)(row + 384 + c)     = __halves2bfloat162(lx, ly);
    *(__nv_bfloat162*)(row + 384 + c + 2) = __halves2bfloat162(lz, lw);
}

// Bt[n, c], c in [0,3K): [Bhi ; Bhi ; Blo] (weights transposed to N-major)
__global__ void wprep(const float* __restrict__ W, __nv_bfloat16* __restrict__ Bt,
                      int K, int N, int Kc) {
    size_t idx = (size_t)blockIdx.x * 256 + threadIdx.x;
    if (idx >= (size_t)N * Kc) return;
    int n = (int)(idx / Kc), c = (int)(idx % Kc);
    int k = (c < K) ? c : ((c < 2 * K) ? c - K : c - 2 * K);
    float w = W[(size_t)k * N + n];
    __nv_bfloat16 h = __float2bfloat16(w);
    Bt[idx] = (c < 2 * K) ? h : __float2bfloat16(w - __bfloat162float(h));
}

__global__ void counts_kernel(const int* __restrict__ edges, float* __restrict__ cnt) {
    int t = blockIdx.x * 256 + threadIdx.x;
    if (t >= T_N) return;
    atomicAdd(&cnt[edges[2*t]], 1.0f);
    atomicAdd(&cnt[edges[2*t + 1]], 1.0f);
}

__global__ void pscale_conv(const float4* __restrict__ pooled, const float* __restrict__ cnt,
                            __nv_bfloat16* __restrict__ p2) {
    int i = blockIdx.x * 256 + threadIdx.x;
    if (i >= O_N * (HID / 4)) return;
    int r = i >> 7;
    float c = fminf(fmaxf(cnt[r], 1.0f), 50000.0f);
    float s = 1.0f / c;
    float4 v = pooled[i];
    v.x *= s; v.y *= s; v.z *= s; v.w *= s;
    __nv_bfloat16 hx = __float2bfloat16(v.x), hy = __float2bfloat16(v.y);
    __nv_bfloat16 hz = __float2bfloat16(v.z), hw = __float2bfloat16(v.w);
    __nv_bfloat16 lx = __float2bfloat16(v.x - __bfloat162float(hx));
    __nv_bfloat16 ly = __float2bfloat16(v.y - __bfloat162float(hy));
    __nv_bfloat16 lz = __float2bfloat16(v.z - __bfloat162float(hz));
    __nv_bfloat16 lw = __float2bfloat16(v.w - __bfloat162float(hw));
    __nv_bfloat16* row = p2 + (size_t)r * 1024;
    int c0 = (i & 127) * 4;
    *(__nv_bfloat162*)(row + c0)           = __halves2bfloat162(hx, hy);
    *(__nv_bfloat162*)(row + c0 + 2)       = __halves2bfloat162(hz, hw);
    *(__nv_bfloat162*)(row + 512 + c0)     = __halves2bfloat162(lx, ly);
    *(__nv_bfloat162*)(row + 512 + c0 + 2) = __halves2bfloat162(lz, lw);
}

// ---------------- mma.sync bf16-split GEMM ------------------------------------
// CTA 128x128, 4 warps, warp tile 64x64, BK=32, 4-stage cp.async pipeline.
// Effective K' = Kc (hi/lo remap: A col = kp<twoK ? kp : kp-twoK).
// EPI 0: fp32 store to outf[row*ostride + col]
// EPI 1: hi/lo bf16 store into outh[row*2*K2 + col] / +K2
// EPI 2: GEMM2 router (col<512 -> s-scatter, 512..639 -> newp, >=640 -> o-scatter)
#define BM 128
#define BN 128
#define BK 32
#define STG 4
#define STG_ELEM 8192          // (BM+BN)*BK bf16 elements per stage

template<int EPI>
__global__ void __launch_bounds__(128, 2)
mma_gemm(const __nv_bfloat16* __restrict__ A, const __nv_bfloat16* __restrict__ Bt,
         const float* __restrict__ bias, float* __restrict__ outf,
         __nv_bfloat16* __restrict__ outh,
         int M, int twoK, int strideA, int Kc, int ostride, int K2,
         const int* __restrict__ edges, float* __restrict__ pooled,
         float* __restrict__ newp)
{
    extern __shared__ __nv_bfloat16 smem[];   // STG * STG_ELEM

    const int tid  = threadIdx.x;
    const int wid  = tid >> 5;
    const int lane = tid & 31;
    const int m0   = blockIdx.y * BM;
    const int n0   = blockIdx.x * BN;
    const int wm   = (wid >> 1) * 64;   // warp M offset (2x2 warp grid)
    const int wn   = (wid & 1) * 64;    // warp N offset

    float acc[4][8][4];
    #pragma unroll
    for (int i = 0; i < 4; i++)
        #pragma unroll
        for (int j = 0; j < 8; j++)
            #pragma unroll
            for (int k = 0; k < 4; k++) acc[i][j][k] = 0.f;

    auto ld_tile = [&](int it, int buf) {
        const int kp = it * BK;
        const int ac = (kp < twoK) ? kp : kp - twoK;
        uint32_t sa = smem_u32(smem + buf * STG_ELEM);
        uint32_t sb = sa + 8192;                      // bytes (4096 elems * 2)
        #pragma unroll
        for (int t = 0; t < 4; t++) {                 // A: 128 rows x 4 chunks(16B)
            int s = tid + t * 128;
            int row = s >> 2, ch = s & 3;
            uint32_t phys = row * 64 + ((ch ^ ((row >> 1) & 3)) << 4);
            int gr = m0 + row;
            cp_async16(sa + phys,
                       A + (size_t)(gr < M ? gr : 0) * strideA + ac + ch * 8,
                       gr < M ? 16 : 0);
        }
        #pragma unroll
        for (int t = 0; t < 4; t++) {                 // B: rows n0..n0+127
            int s = tid + t * 128;
            int row = s >> 2, ch = s & 3;
            uint32_t phys = row * 64 + ((ch ^ ((row >> 1) & 3)) << 4);
            cp_async16(sb + phys, Bt + (size_t)(n0 + row) * Kc + kp + ch * 8, 16);
        }
    };

    const int NC = Kc / BK;
    #pragma unroll
    for (int i = 0; i < STG - 1; i++) {
        ld_tile(i, i);
        asm volatile("cp.async.commit_group;" ::: "memory");
    }

    for (int it = 0; it < NC; it++) {
        asm volatile("cp.async.wait_group 2;" ::: "memory");
        __syncthreads();
        if (it + STG - 1 < NC) ld_tile(it + STG - 1, (it + STG - 1) & 3);
        asm volatile("cp.async.commit_group;" ::: "memory");

        const int buf = it & 3;
        const uint32_t sa = smem_u32(smem + buf * STG_ELEM);
        const uint32_t sb = sa + 8192;
        #pragma unroll
        for (int ks = 0; ks < 2; ks++) {
            uint32_t a[4][4], b[8][2];
            #pragma unroll
            for (int mf = 0; mf < 4; mf++) {
                int row = wm + mf * 16 + (lane & 15);
                int ch  = ks * 2 + (lane >> 4);
                uint32_t addr = sa + row * 64 + ((ch ^ ((row >> 1) & 3)) << 4);
                ldm_x4(a[mf][0], a[mf][1], a[mf][2], a[mf][3], addr);
            }
            #pragma unroll
            for (int bi = 0; bi < 4; bi++) {
                int row = wn + bi * 16 + (lane & 15);
                int ch  = ks * 2 + (lane >> 4);
                uint32_t addr = sb + row * 64 + ((ch ^ ((row >> 1) & 3)) << 4);
                uint32_t r0, r1, r2, r3;
                ldm_x4(r0, r1, r2, r3, addr);
                b[bi*2+0][0] = r0; b[bi*2+0][1] = r2;   // n 0-7 of this n16
                b[bi*2+1][0] = r1; b[bi*2+1][1] = r3;   // n 8-15
            }
            #pragma unroll
            for (int mf = 0; mf < 4; mf++)
                #pragma unroll
                for (int nf = 0; nf < 8; nf++)
                    mma_bf16(acc[mf][nf], a[mf], b[nf]);
        }
    }

    // ---------------- epilogue ------------------------------------------------
    float bc[8][2];
    #pragma unroll
    for (int nf = 0; nf < 8; nf++) {
        float2 bv = __ldg((const float2*)&bias[n0 + wn + nf * 8 + (lane & 3) * 2]);
        bc[nf][0] = bv.x; bc[nf][1] = bv.y;
    }

    #pragma unroll
    for (int mf = 0; mf < 4; mf++) {
        #pragma unroll
        for (int rh = 0; rh < 2; rh++) {
            const int gr = m0 + wm + mf * 16 + (lane >> 2) + rh * 8;
            if (gr >= M) continue;
            int es = 0, eo = 0;
            if (EPI == 2) { es = edges[2*gr]; eo = edges[2*gr + 1]; }
            #pragma unroll
            for (int nf = 0; nf < 8; nf++) {
                const int col = n0 + wn + nf * 8 + (lane & 3) * 2;
                float v0 = fmaxf(acc[mf][nf][rh*2+0] + bc[nf][0], 0.f);
                float v1 = fmaxf(acc[mf][nf][rh*2+1] + bc[nf][1], 0.f);
                if (EPI == 0) {
                    float2 v = make_float2(v0, v1);
                    *(float2*)&outf[(size_t)gr * ostride + col] = v;
                } else if (EPI == 1) {
                    __nv_bfloat16 h0 = __float2bfloat16(v0), h1 = __float2bfloat16(v1);
                    __nv_bfloat16 l0 = __float2bfloat16(v0 - __bfloat162float(h0));
                    __nv_bfloat16 l1 = __float2bfloat16(v1 - __bfloat162float(h1));
                    __nv_bfloat16* p = outh + (size_t)gr * (2 * K2) + col;
                    *(__nv_bfloat162*)p        = __halves2bfloat162(h0, h1);
                    *(__nv_bfloat162*)(p + K2) = __halves2bfloat162(l0, l1);
                } else {
                    if (col < HID) {
                        red_add2(&pooled[(size_t)es * HID + col], v0, v1);
                    } else if (col < HID + DOUT) {
                        float2 v = make_float2(v0, v1);
                        *(float2*)&newp[(size_t)gr * DOUT + (col - HID)] = v;
                    } else {
                        red_add2(&pooled[(size_t)eo * HID + (col - HID - DOUT)], v0, v1);
                    }
                }
            }
        }
    }
}

// ---------------- launch ------------------------------------------------------
extern "C" void kernel_launch(void* const* d_in, const int* in_sizes, int n_in,
                              void* d_out, int out_size) {
    const float* obj  = (const float*)d_in[0];
    const float* pred = (const float*)d_in[1];
    const int*   edges= (const int*)  d_in[2];
    const float* W1a  = (const float*)d_in[3];
    const float* b1a  = (const float*)d_in[4];
    const float* W1b  = (const float*)d_in[5];
    const float* b1b  = (const float*)d_in[6];
    const float* W2a  = (const float*)d_in[7];
    const float* b2a  = (const float*)d_in[8];
    const float* W2b  = (const float*)d_in[9];
    const float* b2b  = (const float*)d_in[10];

    float* out     = (float*)d_out;
    float* new_obj = out;                       // [O, 128]
    float* new_p   = out + (size_t)O_N * DOUT;  // [T, 128]

    __nv_bfloat16 *curt, *h2K, *p2, *h2, *bt1, *bt2, *bt3, *bt4;
    float *pooled, *cnt;
    cudaGetSymbolAddress((void**)&curt,   g_curt);
    cudaGetSymbolAddress((void**)&h2K,    g_h);
    cudaGetSymbolAddress((void**)&pooled, g_pool);
    cudaGetSymbolAddress((void**)&p2,     g_pool2);
    cudaGetSymbolAddress((void**)&h2,     g_h2);
    cudaGetSymbolAddress((void**)&cnt,    g_cnt);
    cudaGetSymbolAddress((void**)&bt1,    g_bt1);
    cudaGetSymbolAddress((void**)&bt2,    g_bt2);
    cudaGetSymbolAddress((void**)&bt3,    g_bt3);
    cudaGetSymbolAddress((void**)&bt4,    g_bt4);

    const int SMEM = STG * STG_ELEM * 2;   // 65536 bytes
    cudaFuncSetAttribute(mma_gemm<0>, cudaFuncAttributeMaxDynamicSharedMemorySize, SMEM);
    cudaFuncSetAttribute(mma_gemm<1>, cudaFuncAttributeMaxDynamicSharedMemorySize, SMEM);
    cudaFuncSetAttribute(mma_gemm<2>, cudaFuncAttributeMaxDynamicSharedMemorySize, SMEM);

    cudaMemsetAsync(pooled, 0, (size_t)O_N * HID * sizeof(float));
    cudaMemsetAsync(cnt,    0, (size_t)O_N * sizeof(float));

    {   size_t n = (size_t)512 * 1152;
        wprep<<<(unsigned)((n + 255) / 256), 256>>>(W1a, bt1, 384, 512, 1152); }
    {   size_t n = (size_t)1152 * 1536;
        wprep<<<(unsigned)((n + 255) / 256), 256>>>(W1b, bt2, 512, 1152, 1536); }
    {   size_t n = (size_t)512 * 1536;
        wprep<<<(unsigned)((n + 255) / 256), 256>>>(W2a, bt3, 512, 512, 1536); }
    {   size_t n = (size_t)128 * 1536;
        wprep<<<(unsigned)((n + 255) / 256), 256>>>(W2b, bt4, 512, 128, 1536); }

    gather_conv<<<(T_N * 96 + 255) / 256, 256>>>(
        (const float4*)obj, (const float4*)pred, edges, curt);
    counts_kernel<<<(T_N + 255) / 256, 256>>>(edges, cnt);

    const int MT_T = (T_N + 127) / 128;   // 1563
    const int MT_O = (O_N + 127) / 128;   // 391

    // GEMM1: h = relu(curt @ W1a + b1a) -> hi/lo bf16   (grid x=N tiles for L2 A reuse)
    mma_gemm<1><<<dim3(4, MT_T), 128, SMEM>>>(
        curt, bt1, b1a, nullptr, h2K,
        T_N, 768, 768, 1152, 0, HID, nullptr, nullptr, nullptr);

    // GEMM2: new_t = relu(h @ W1b + b1b) -> scatter s/o + store new_p (one launch)
    mma_gemm<2><<<dim3(9, MT_T), 128, SMEM>>>(
        h2K, bt2, b1b, nullptr, nullptr,
        T_N, 1024, 1024, 1536, 0, 0, edges, pooled, new_p);

    pscale_conv<<<(O_N * (HID / 4) + 255) / 256, 256>>>((const float4*)pooled, cnt, p2);

    // GEMM3: h2 = relu(pooled @ W2a + b2a) -> hi/lo bf16
    mma_gemm<1><<<dim3(4, MT_O), 128, SMEM>>>(
        p2, bt3, b2a, nullptr, h2,
        O_N, 1024, 1024, 1536, 0, HID, nullptr, nullptr, nullptr);

    // GEMM4: new_obj = relu(h2 @ W2b + b2b)
    mma_gemm<0><<<dim3(1, MT_O), 128, SMEM>>>(
        h2, bt4, b2b, new_obj, nullptr,
        O_N, 1024, 1024, 1536, DOUT, 0, nullptr, nullptr, nullptr);
}

// round 5
// speedup vs baseline: 3.0627x; 1.3518x over previous
#include <cuda_runtime.h>
#include <cuda_bf16.h>
#include <cuda_fp16.h>
#include <cstdint>

#define O_N   50000
#define T_N   200000
#define DIN   128
#define HID   512
#define DOUT  128

// ---------------- device scratch (allocation-free rule) -----------------------
__device__ __half         g_curt[(size_t)T_N * 768];   // [T, 2*384] fp16 hi|lo
__device__ __half         g_h   [(size_t)T_N * 1024];  // [T, 2*512] fp16 hi|lo
__device__ float          g_pool[(size_t)O_N * HID];   // fp32 accum
__device__ __nv_bfloat16  g_pool2[(size_t)O_N * 1024]; // [O, 2*512] bf16 hi|lo
__device__ __nv_bfloat16  g_h2  [(size_t)O_N * 1024];  // [O, 2*512] bf16 hi|lo
__device__ float          g_cnt [O_N];
__device__ __half         g_bt1[(size_t)512  * 768];   // [N,2K] = [Bh;Bh] fp16
__device__ __half         g_bt2[(size_t)1152 * 1024];  // [N,2K] = [Bh;Bh] fp16
__device__ __nv_bfloat16  g_bt3[(size_t)512  * 1536];  // [N,3K] = [Bhi;Bhi;Blo] bf16
__device__ __nv_bfloat16  g_bt4[(size_t)128  * 1536];

// ---------------- PTX helpers -------------------------------------------------
__device__ __forceinline__ uint32_t smem_u32(const void* p) {
    uint32_t a;
    asm("{ .reg .u64 t; cvta.to.shared.u64 t, %1; cvt.u32.u64 %0, t; }" : "=r"(a) : "l"(p));
    return a;
}
__device__ __forceinline__ void cp_async16(uint32_t dst, const void* src, int sz) {
    asm volatile("cp.async.cg.shared.global [%0], [%1], 16, %2;"
                 :: "r"(dst), "l"(src), "r"(sz));
}
__device__ __forceinline__ void ldm_x4(uint32_t& r0, uint32_t& r1, uint32_t& r2,
                                       uint32_t& r3, uint32_t addr) {
    asm volatile("ldmatrix.sync.aligned.m8n8.x4.shared.b16 {%0,%1,%2,%3}, [%4];"
                 : "=r"(r0), "=r"(r1), "=r"(r2), "=r"(r3) : "r"(addr));
}
template<int DT>
__device__ __forceinline__ void mma_any(float* c, const uint32_t* a, const uint32_t* b) {
    if (DT == 0)
        asm volatile("mma.sync.aligned.m16n8k16.row.col.f32.bf16.bf16.f32 "
                     "{%0,%1,%2,%3}, {%4,%5,%6,%7}, {%8,%9}, {%0,%1,%2,%3};"
                     : "+f"(c[0]), "+f"(c[1]), "+f"(c[2]), "+f"(c[3])
                     : "r"(a[0]), "r"(a[1]), "r"(a[2]), "r"(a[3]), "r"(b[0]), "r"(b[1]));
    else
        asm volatile("mma.sync.aligned.m16n8k16.row.col.f32.f16.f16.f32 "
                     "{%0,%1,%2,%3}, {%4,%5,%6,%7}, {%8,%9}, {%0,%1,%2,%3};"
                     : "+f"(c[0]), "+f"(c[1]), "+f"(c[2]), "+f"(c[3])
                     : "r"(a[0]), "r"(a[1]), "r"(a[2]), "r"(a[3]), "r"(b[0]), "r"(b[1]));
}
__device__ __forceinline__ void red_add2(float* p, float a, float b) {
    asm volatile("red.global.add.v2.f32 [%0], {%1,%2};"
                 :: "l"(p), "f"(a), "f"(b) : "memory");
}

// ---------------- feeders -----------------------------------------------------
// cur_t as fp16 [hi(384) | lo(384)] : exact sum = fp32 value
__global__ void gather_conv(const float4* __restrict__ obj, const float4* __restrict__ pred,
                            const int* __restrict__ edges, __half* __restrict__ curt) {
    int i = blockIdx.x * 256 + threadIdx.x;
    if (i >= T_N * 96) return;
    int r = i / 96, j = i - r * 96;
    float4 v;
    if (j < 32)       v = obj[(size_t)edges[2*r]     * 32 + j];
    else if (j < 64)  v = pred[(size_t)r             * 32 + (j - 32)];
    else              v = obj[(size_t)edges[2*r + 1] * 32 + (j - 64)];
    __half hx = __float2half_rn(v.x), hy = __float2half_rn(v.y);
    __half hz = __float2half_rn(v.z), hw = __float2half_rn(v.w);
    __half lx = __float2half_rn(v.x - __half2float(hx));
    __half ly = __float2half_rn(v.y - __half2float(hy));
    __half lz = __float2half_rn(v.z - __half2float(hz));
    __half lw = __float2half_rn(v.w - __half2float(hw));
    __half* row = curt + (size_t)r * 768;
    int c = j * 4;
    *(__half2*)(row + c)           = __halves2half2(hx, hy);
    *(__half2*)(row + c + 2)       = __halves2half2(hz, hw);
    *(__half2*)(row + 384 + c)     = __halves2half2(lx, ly);
    *(__half2*)(row + 384 + c + 2) = __halves2half2(lz, lw);
}

// fp16 2-term weights: Bt[n, c], c in [0,2K): [Bh ; Bh] (repeated)
__global__ void wprep2(const float* __restrict__ W, __half* __restrict__ Bt,
                       int K, int N) {
    int Kc = 2 * K;
    size_t idx = (size_t)blockIdx.x * 256 + threadIdx.x;
    if (idx >= (size_t)N * Kc) return;
    int n = (int)(idx / Kc), c = (int)(idx % Kc);
    int k = (c < K) ? c : c - K;
    Bt[idx] = __float2half_rn(W[(size_t)k * N + n]);
}

// bf16 3-term weights: Bt[n, c], c in [0,3K): [Bhi ; Bhi ; Blo]
__global__ void wprep3(const float* __restrict__ W, __nv_bfloat16* __restrict__ Bt,
                       int K, int N, int Kc) {
    size_t idx = (size_t)blockIdx.x * 256 + threadIdx.x;
    if (idx >= (size_t)N * Kc) return;
    int n = (int)(idx / Kc), c = (int)(idx % Kc);
    int k = (c < K) ? c : ((c < 2 * K) ? c - K : c - 2 * K);
    float w = W[(size_t)k * N + n];
    __nv_bfloat16 h = __float2bfloat16(w);
    Bt[idx] = (c < 2 * K) ? h : __float2bfloat16(w - __bfloat162float(h));
}

__global__ void counts_kernel(const int* __restrict__ edges, float* __restrict__ cnt) {
    int t = blockIdx.x * 256 + threadIdx.x;
    if (t >= T_N) return;
    atomicAdd(&cnt[edges[2*t]], 1.0f);
    atomicAdd(&cnt[edges[2*t + 1]], 1.0f);
}

__global__ void pscale_conv(const float4* __restrict__ pooled, const float* __restrict__ cnt,
                            __nv_bfloat16* __restrict__ p2) {
    int i = blockIdx.x * 256 + threadIdx.x;
    if (i >= O_N * (HID / 4)) return;
    int r = i >> 7;
    float c = fminf(fmaxf(cnt[r], 1.0f), 50000.0f);
    float s = 1.0f / c;
    float4 v = pooled[i];
    v.x *= s; v.y *= s; v.z *= s; v.w *= s;
    __nv_bfloat16 hx = __float2bfloat16(v.x), hy = __float2bfloat16(v.y);
    __nv_bfloat16 hz = __float2bfloat16(v.z), hw = __float2bfloat16(v.w);
    __nv_bfloat16 lx = __float2bfloat16(v.x - __bfloat162float(hx));
    __nv_bfloat16 ly = __float2bfloat16(v.y - __bfloat162float(hy));
    __nv_bfloat16 lz = __float2bfloat16(v.z - __bfloat162float(hz));
    __nv_bfloat16 lw = __float2bfloat16(v.w - __bfloat162float(hw));
    __nv_bfloat16* row = p2 + (size_t)r * 1024;
    int c0 = (i & 127) * 4;
    *(__nv_bfloat162*)(row + c0)           = __halves2bfloat162(hx, hy);
    *(__nv_bfloat162*)(row + c0 + 2)       = __halves2bfloat162(hz, hw);
    *(__nv_bfloat162*)(row + 512 + c0)     = __halves2bfloat162(lx, ly);
    *(__nv_bfloat162*)(row + 512 + c0 + 2) = __halves2bfloat162(lz, lw);
}

// ---------------- mma.sync split GEMM -----------------------------------------
// CTA 128x128, 4 warps (64x64 tiles), BK=32, 4-stage cp.async pipeline.
// DT=0: bf16 ops, DT=1: fp16 ops. A col remap: kp<twoK ? kp : kp-twoK.
// EPI 0: fp32 store      EPI 1: hi/lo (dtype DT) store      EPI 2: GEMM2 router
#define BM 128
#define BN 128
#define BK 32
#define STG 4
#define STG_ELEM 8192          // (BM+BN)*BK 2-byte elements per stage

template<int EPI, int DT>
__global__ void __launch_bounds__(128, 2)
mma_gemm(const void* __restrict__ Av, const void* __restrict__ Btv,
         const float* __restrict__ bias, float* __restrict__ outf,
         void* __restrict__ outhv,
         int M, int twoK, int strideA, int Kc, int ostride, int K2,
         const int* __restrict__ edges, float* __restrict__ pooled,
         float* __restrict__ newp)
{
    extern __shared__ uint16_t smem[];   // STG * STG_ELEM

    const uint16_t* A  = (const uint16_t*)Av;
    const uint16_t* Bt = (const uint16_t*)Btv;

    const int tid  = threadIdx.x;
    const int wid  = tid >> 5;
    const int lane = tid & 31;
    const int m0   = blockIdx.y * BM;
    const int n0   = blockIdx.x * BN;
    const int wm   = (wid >> 1) * 64;
    const int wn   = (wid & 1) * 64;

    float acc[4][8][4];
    #pragma unroll
    for (int i = 0; i < 4; i++)
        #pragma unroll
        for (int j = 0; j < 8; j++)
            #pragma unroll
            for (int k = 0; k < 4; k++) acc[i][j][k] = 0.f;

    auto ld_tile = [&](int it, int buf) {
        const int kp = it * BK;
        const int ac = (kp < twoK) ? kp : kp - twoK;
        uint32_t sa = smem_u32(smem + buf * STG_ELEM);
        uint32_t sb = sa + 8192;                      // bytes
        #pragma unroll
        for (int t = 0; t < 4; t++) {                 // A: 128 rows x 4 chunks(16B)
            int s = tid + t * 128;
            int row = s >> 2, ch = s & 3;
            uint32_t phys = row * 64 + ((ch ^ ((row >> 1) & 3)) << 4);
            int gr = m0 + row;
            cp_async16(sa + phys,
                       A + (size_t)(gr < M ? gr : 0) * strideA + ac + ch * 8,
                       gr < M ? 16 : 0);
        }
        #pragma unroll
        for (int t = 0; t < 4; t++) {                 // B: rows n0..n0+127
            int s = tid + t * 128;
            int row = s >> 2, ch = s & 3;
            uint32_t phys = row * 64 + ((ch ^ ((row >> 1) & 3)) << 4);
            cp_async16(sb + phys, Bt + (size_t)(n0 + row) * Kc + kp + ch * 8, 16);
        }
    };

    const int NC = Kc / BK;
    #pragma unroll
    for (int i = 0; i < STG - 1; i++) {
        ld_tile(i, i);
        asm volatile("cp.async.commit_group;" ::: "memory");
    }

    for (int it = 0; it < NC; it++) {
        asm volatile("cp.async.wait_group 2;" ::: "memory");
        __syncthreads();
        if (it + STG - 1 < NC) ld_tile(it + STG - 1, (it + STG - 1) & 3);
        asm volatile("cp.async.commit_group;" ::: "memory");

        const int buf = it & 3;
        const uint32_t sa = smem_u32(smem + buf * STG_ELEM);
        const uint32_t sb = sa + 8192;
        #pragma unroll
        for (int ks = 0; ks < 2; ks++) {
            uint32_t a[4][4], b[8][2];
            #pragma unroll
            for (int mf = 0; mf < 4; mf++) {
                int row = wm + mf * 16 + (lane & 15);
                int ch  = ks * 2 + (lane >> 4);
                uint32_t addr = sa + row * 64 + ((ch ^ ((row >> 1) & 3)) << 4);
                ldm_x4(a[mf][0], a[mf][1], a[mf][2], a[mf][3], addr);
            }
            #pragma unroll
            for (int bi = 0; bi < 4; bi++) {
                int row = wn + bi * 16 + (lane & 15);
                int ch  = ks * 2 + (lane >> 4);
                uint32_t addr = sb + row * 64 + ((ch ^ ((row >> 1) & 3)) << 4);
                uint32_t r0, r1, r2, r3;
                ldm_x4(r0, r1, r2, r3, addr);
                b[bi*2+0][0] = r0; b[bi*2+0][1] = r2;
                b[bi*2+1][0] = r1; b[bi*2+1][1] = r3;
            }
            #pragma unroll
            for (int mf = 0; mf < 4; mf++)
                #pragma unroll
                for (int nf = 0; nf < 8; nf++)
                    mma_any<DT>(acc[mf][nf], a[mf], b[nf]);
        }
    }

    // ---------------- epilogue ------------------------------------------------
    float bc[8][2];
    #pragma unroll
    for (int nf = 0; nf < 8; nf++) {
        float2 bv = __ldg((const float2*)&bias[n0 + wn + nf * 8 + (lane & 3) * 2]);
        bc[nf][0] = bv.x; bc[nf][1] = bv.y;
    }

    #pragma unroll
    for (int mf = 0; mf < 4; mf++) {
        #pragma unroll
        for (int rh = 0; rh < 2; rh++) {
            const int gr = m0 + wm + mf * 16 + (lane >> 2) + rh * 8;
            if (gr >= M) continue;
            int es = 0, eo = 0;
            if (EPI == 2) { es = edges[2*gr]; eo = edges[2*gr + 1]; }
            #pragma unroll
            for (int nf = 0; nf < 8; nf++) {
                const int col = n0 + wn + nf * 8 + (lane & 3) * 2;
                float v0 = fmaxf(acc[mf][nf][rh*2+0] + bc[nf][0], 0.f);
                float v1 = fmaxf(acc[mf][nf][rh*2+1] + bc[nf][1], 0.f);
                if (EPI == 0) {
                    float2 v = make_float2(v0, v1);
                    *(float2*)&outf[(size_t)gr * ostride + col] = v;
                } else if (EPI == 1) {
                    if (DT == 1) {
                        __half h0 = __float2half_rn(v0), h1 = __float2half_rn(v1);
                        __half l0 = __float2half_rn(v0 - __half2float(h0));
                        __half l1 = __float2half_rn(v1 - __half2float(h1));
                        __half* p = (__half*)outhv + (size_t)gr * (2 * K2) + col;
                        *(__half2*)p        = __halves2half2(h0, h1);
                        *(__half2*)(p + K2) = __halves2half2(l0, l1);
                    } else {
                        __nv_bfloat16 h0 = __float2bfloat16(v0), h1 = __float2bfloat16(v1);
                        __nv_bfloat16 l0 = __float2bfloat16(v0 - __bfloat162float(h0));
                        __nv_bfloat16 l1 = __float2bfloat16(v1 - __bfloat162float(h1));
                        __nv_bfloat16* p = (__nv_bfloat16*)outhv + (size_t)gr * (2 * K2) + col;
                        *(__nv_bfloat162*)p        = __halves2bfloat162(h0, h1);
                        *(__nv_bfloat162*)(p + K2) = __halves2bfloat162(l0, l1);
                    }
                } else {
                    if (col < HID) {
                        red_add2(&pooled[(size_t)es * HID + col], v0, v1);
                    } else if (col < HID + DOUT) {
                        float2 v = make_float2(v0, v1);
                        *(float2*)&newp[(size_t)gr * DOUT + (col - HID)] = v;
                    } else {
                        red_add2(&pooled[(size_t)eo * HID + (col - HID - DOUT)], v0, v1);
                    }
                }
            }
        }
    }
}

// ---------------- launch ------------------------------------------------------
extern "C" void kernel_launch(void* const* d_in, const int* in_sizes, int n_in,
                              void* d_out, int out_size) {
    const float* obj  = (const float*)d_in[0];
    const float* pred = (const float*)d_in[1];
    const int*   edges= (const int*)  d_in[2];
    const float* W1a  = (const float*)d_in[3];
    const float* b1a  = (const float*)d_in[4];
    const float* W1b  = (const float*)d_in[5];
    const float* b1b  = (const float*)d_in[6];
    const float* W2a  = (const float*)d_in[7];
    const float* b2a  = (const float*)d_in[8];
    const float* W2b  = (const float*)d_in[9];
    const float* b2b  = (const float*)d_in[10];

    float* out     = (float*)d_out;
    float* new_obj = out;                       // [O, 128]
    float* new_p   = out + (size_t)O_N * DOUT;  // [T, 128]

    __half *curt, *h16, *bt1, *bt2;
    __nv_bfloat16 *p2, *h2, *bt3, *bt4;
    float *pooled, *cnt;
    cudaGetSymbolAddress((void**)&curt,   g_curt);
    cudaGetSymbolAddress((void**)&h16,    g_h);
    cudaGetSymbolAddress((void**)&pooled, g_pool);
    cudaGetSymbolAddress((void**)&p2,     g_pool2);
    cudaGetSymbolAddress((void**)&h2,     g_h2);
    cudaGetSymbolAddress((void**)&cnt,    g_cnt);
    cudaGetSymbolAddress((void**)&bt1,    g_bt1);
    cudaGetSymbolAddress((void**)&bt2,    g_bt2);
    cudaGetSymbolAddress((void**)&bt3,    g_bt3);
    cudaGetSymbolAddress((void**)&bt4,    g_bt4);

    const int SMEM = STG * STG_ELEM * 2;   // 65536 bytes
    cudaFuncSetAttribute((const void*)mma_gemm<1,1>, cudaFuncAttributeMaxDynamicSharedMemorySize, SMEM);
    cudaFuncSetAttribute((const void*)mma_gemm<2,1>, cudaFuncAttributeMaxDynamicSharedMemorySize, SMEM);
    cudaFuncSetAttribute((const void*)mma_gemm<1,0>, cudaFuncAttributeMaxDynamicSharedMemorySize, SMEM);
    cudaFuncSetAttribute((const void*)mma_gemm<0,0>, cudaFuncAttributeMaxDynamicSharedMemorySize, SMEM);

    cudaMemsetAsync(pooled, 0, (size_t)O_N * HID * sizeof(float));
    cudaMemsetAsync(cnt,    0, (size_t)O_N * sizeof(float));

    {   size_t n = (size_t)512 * 768;
        wprep2<<<(unsigned)((n + 255) / 256), 256>>>(W1a, bt1, 384, 512); }
    {   size_t n = (size_t)1152 * 1024;
        wprep2<<<(unsigned)((n + 255) / 256), 256>>>(W1b, bt2, 512, 1152); }
    {   size_t n = (size_t)512 * 1536;
        wprep3<<<(unsigned)((n + 255) / 256), 256>>>(W2a, bt3, 512, 512, 1536); }
    {   size_t n = (size_t)128 * 1536;
        wprep3<<<(unsigned)((n + 255) / 256), 256>>>(W2b, bt4, 512, 128, 1536); }

    gather_conv<<<(T_N * 96 + 255) / 256, 256>>>(
        (const float4*)obj, (const float4*)pred, edges, curt);
    counts_kernel<<<(T_N + 255) / 256, 256>>>(edges, cnt);

    const int MT_T = (T_N + 127) / 128;   // 1563
    const int MT_O = (O_N + 127) / 128;   // 391

    // GEMM1 (fp16 2-term, Kc=768): h = relu(curt @ W1a + b1a) -> fp16 hi/lo
    mma_gemm<1,1><<<dim3(4, MT_T), 128, SMEM>>>(
        curt, bt1, b1a, nullptr, h16,
        T_N, 768, 768, 768, 0, HID, nullptr, nullptr, nullptr);

    // GEMM2 (fp16 2-term, Kc=1024): scatter s/o + store new_p
    mma_gemm<2,1><<<dim3(9, MT_T), 128, SMEM>>>(
        h16, bt2, b1b, nullptr, nullptr,
        T_N, 1024, 1024, 1024, 0, 0, edges, pooled, new_p);

    pscale_conv<<<(O_N * (HID / 4) + 255) / 256, 256>>>((const float4*)pooled, cnt, p2);

    // GEMM3 (bf16 3-term, Kc=1536): h2 = relu(pooled @ W2a + b2a) -> bf16 hi/lo
    mma_gemm<1,0><<<dim3(4, MT_O), 128, SMEM>>>(
        p2, bt3, b2a, nullptr, h2,
        O_N, 1024, 1024, 1536, 0, HID, nullptr, nullptr, nullptr);

    // GEMM4 (bf16 3-term): new_obj = relu(h2 @ W2b + b2b)
    mma_gemm<0,0><<<dim3(1, MT_O), 128, SMEM>>>(
        h2, bt4, b2b, new_obj, nullptr,
        O_N, 1024, 1024, 1536, DOUT, 0, nullptr, nullptr, nullptr);
}

// round 6
// speedup vs baseline: 5.1576x; 1.6840x over previous
#include <cuda_runtime.h>
#include <cuda_fp16.h>
#include <cstdint>

#define O_N   50000
#define T_N   200000
#define DIN   128
#define HID   512
#define DOUT  128

// ---------------- device scratch (allocation-free rule) -----------------------
__device__ __half  g_curt[(size_t)T_N * 384];    // [T, 384]  fp16
__device__ __half  g_h   [(size_t)T_N * 512];    // [T, 512]  fp16
__device__ float   g_pool[(size_t)O_N * HID];    // fp32 accum
__device__ __half  g_pool2[(size_t)O_N * 1024];  // [O, 2*512] fp16 hi|lo
__device__ __half  g_h2  [(size_t)O_N * 1024];   // [O, 2*512] fp16 hi|lo
__device__ float   g_cnt [O_N];
__device__ __half  g_bt1[(size_t)512  * 384];    // [N,K]  fp16
__device__ __half  g_bt2[(size_t)1152 * 512];    // [N,K]  fp16
__device__ __half  g_bt3[(size_t)512  * 1024];   // [N,2K] = [Bh;Bh]
__device__ __half  g_bt4[(size_t)128  * 1024];   // [N,2K] = [Bh;Bh]

// ---------------- PTX helpers -------------------------------------------------
__device__ __forceinline__ uint32_t smem_u32(const void* p) {
    uint32_t a;
    asm("{ .reg .u64 t; cvta.to.shared.u64 t, %1; cvt.u32.u64 %0, t; }" : "=r"(a) : "l"(p));
    return a;
}
__device__ __forceinline__ void cp_async16(uint32_t dst, const void* src, int sz) {
    asm volatile("cp.async.cg.shared.global [%0], [%1], 16, %2;"
                 :: "r"(dst), "l"(src), "r"(sz));
}
__device__ __forceinline__ void ldm_x4(uint32_t& r0, uint32_t& r1, uint32_t& r2,
                                       uint32_t& r3, uint32_t addr) {
    asm volatile("ldmatrix.sync.aligned.m8n8.x4.shared.b16 {%0,%1,%2,%3}, [%4];"
                 : "=r"(r0), "=r"(r1), "=r"(r2), "=r"(r3) : "r"(addr));
}
__device__ __forceinline__ void mma_f16(float* c, const uint32_t* a, const uint32_t* b) {
    asm volatile("mma.sync.aligned.m16n8k16.row.col.f32.f16.f16.f32 "
                 "{%0,%1,%2,%3}, {%4,%5,%6,%7}, {%8,%9}, {%0,%1,%2,%3};"
                 : "+f"(c[0]), "+f"(c[1]), "+f"(c[2]), "+f"(c[3])
                 : "r"(a[0]), "r"(a[1]), "r"(a[2]), "r"(a[3]), "r"(b[0]), "r"(b[1]));
}
__device__ __forceinline__ void red_add2(float* p, float a, float b) {
    asm volatile("red.global.add.v2.f32 [%0], {%1,%2};"
                 :: "l"(p), "f"(a), "f"(b) : "memory");
}

// ---------------- feeders -----------------------------------------------------
// cur_t as plain fp16 [T, 384]
__global__ void gather_conv(const float4* __restrict__ obj, const float4* __restrict__ pred,
                            const int* __restrict__ edges, __half* __restrict__ curt) {
    int i = blockIdx.x * 256 + threadIdx.x;
    if (i >= T_N * 96) return;
    int r = i / 96, j = i - r * 96;
    float4 v;
    if (j < 32)       v = obj[(size_t)edges[2*r]     * 32 + j];
    else if (j < 64)  v = pred[(size_t)r             * 32 + (j - 32)];
    else              v = obj[(size_t)edges[2*r + 1] * 32 + (j - 64)];
    __half2 lo = __halves2half2(__float2half_rn(v.x), __float2half_rn(v.y));
    __half2 hi = __halves2half2(__float2half_rn(v.z), __float2half_rn(v.w));
    __half* row = curt + (size_t)r * 384;
    *(__half2*)(row + j * 4)     = lo;
    *(__half2*)(row + j * 4 + 2) = hi;
}

// plain fp16 transpose: Bt[n,k] = W[k,n]
__global__ void wprep1(const float* __restrict__ W, __half* __restrict__ Bt,
                       int K, int N) {
    size_t idx = (size_t)blockIdx.x * 256 + threadIdx.x;
    if (idx >= (size_t)N * K) return;
    int n = (int)(idx / K), k = (int)(idx % K);
    Bt[idx] = __float2half_rn(W[(size_t)k * N + n]);
}

// fp16 2-term weights: Bt[n, c], c in [0,2K): [Bh ; Bh] (repeated)
__global__ void wprep2(const float* __restrict__ W, __half* __restrict__ Bt,
                       int K, int N) {
    int Kc = 2 * K;
    size_t idx = (size_t)blockIdx.x * 256 + threadIdx.x;
    if (idx >= (size_t)N * Kc) return;
    int n = (int)(idx / Kc), c = (int)(idx % Kc);
    int k = (c < K) ? c : c - K;
    Bt[idx] = __float2half_rn(W[(size_t)k * N + n]);
}

__global__ void counts_kernel(const int* __restrict__ edges, float* __restrict__ cnt) {
    int t = blockIdx.x * 256 + threadIdx.x;
    if (t >= T_N) return;
    atomicAdd(&cnt[edges[2*t]], 1.0f);
    atomicAdd(&cnt[edges[2*t + 1]], 1.0f);
}

// pooled/counts -> fp16 hi/lo pair (exact sum)
__global__ void pscale_conv(const float4* __restrict__ pooled, const float* __restrict__ cnt,
                            __half* __restrict__ p2) {
    int i = blockIdx.x * 256 + threadIdx.x;
    if (i >= O_N * (HID / 4)) return;
    int r = i >> 7;
    float c = fminf(fmaxf(cnt[r], 1.0f), 50000.0f);
    float s = 1.0f / c;
    float4 v = pooled[i];
    v.x *= s; v.y *= s; v.z *= s; v.w *= s;
    __half hx = __float2half_rn(v.x), hy = __float2half_rn(v.y);
    __half hz = __float2half_rn(v.z), hw = __float2half_rn(v.w);
    __half lx = __float2half_rn(v.x - __half2float(hx));
    __half ly = __float2half_rn(v.y - __half2float(hy));
    __half lz = __float2half_rn(v.z - __half2float(hz));
    __half lw = __float2half_rn(v.w - __half2float(hw));
    __half* row = p2 + (size_t)r * 1024;
    int c0 = (i & 127) * 4;
    *(__half2*)(row + c0)           = __halves2half2(hx, hy);
    *(__half2*)(row + c0 + 2)       = __halves2half2(hz, hw);
    *(__half2*)(row + 512 + c0)     = __halves2half2(lx, ly);
    *(__half2*)(row + 512 + c0 + 2) = __halves2half2(lz, lw);
}

// ---------------- mma.sync fp16 GEMM ------------------------------------------
// CTA 128x128, 4 warps (64x64 tiles), BK=32, 4-stage cp.async pipeline.
// EPI 0: fp32 store           EPI 1: fp16 hi/lo store (outh, +K2)
// EPI 2: GEMM2 router         EPI 3: plain fp16 store (outh, ostride)
#define BM 128
#define BN 128
#define BK 32
#define STG 4
#define STG_ELEM 8192          // (BM+BN)*BK 2-byte elements per stage

template<int EPI>
__global__ void __launch_bounds__(128, 2)
mma_gemm(const __half* __restrict__ A, const __half* __restrict__ Bt,
         const float* __restrict__ bias, float* __restrict__ outf,
         __half* __restrict__ outh,
         int M, int strideA, int Kc, int ostride, int K2,
         const int* __restrict__ edges, float* __restrict__ pooled,
         float* __restrict__ newp)
{
    extern __shared__ uint16_t smem[];   // STG * STG_ELEM

    const int tid  = threadIdx.x;
    const int wid  = tid >> 5;
    const int lane = tid & 31;
    const int m0   = blockIdx.y * BM;
    const int n0   = blockIdx.x * BN;
    const int wm   = (wid >> 1) * 64;
    const int wn   = (wid & 1) * 64;

    float acc[4][8][4];
    #pragma unroll
    for (int i = 0; i < 4; i++)
        #pragma unroll
        for (int j = 0; j < 8; j++)
            #pragma unroll
            for (int k = 0; k < 4; k++) acc[i][j][k] = 0.f;

    auto ld_tile = [&](int it, int buf) {
        const int kp = it * BK;
        uint32_t sa = smem_u32(smem + buf * STG_ELEM);
        uint32_t sb = sa + 8192;                      // bytes
        #pragma unroll
        for (int t = 0; t < 4; t++) {                 // A: 128 rows x 4 chunks(16B)
            int s = tid + t * 128;
            int row = s >> 2, ch = s & 3;
            uint32_t phys = row * 64 + ((ch ^ ((row >> 1) & 3)) << 4);
            int gr = m0 + row;
            cp_async16(sa + phys,
                       A + (size_t)(gr < M ? gr : 0) * strideA + kp + ch * 8,
                       gr < M ? 16 : 0);
        }
        #pragma unroll
        for (int t = 0; t < 4; t++) {                 // B: rows n0..n0+127
            int s = tid + t * 128;
            int row = s >> 2, ch = s & 3;
            uint32_t phys = row * 64 + ((ch ^ ((row >> 1) & 3)) << 4);
            cp_async16(sb + phys, Bt + (size_t)(n0 + row) * Kc + kp + ch * 8, 16);
        }
    };

    const int NC = Kc / BK;
    #pragma unroll
    for (int i = 0; i < STG - 1; i++) {
        ld_tile(i, i);
        asm volatile("cp.async.commit_group;" ::: "memory");
    }

    for (int it = 0; it < NC; it++) {
        asm volatile("cp.async.wait_group 2;" ::: "memory");
        __syncthreads();
        if (it + STG - 1 < NC) ld_tile(it + STG - 1, (it + STG - 1) & 3);
        asm volatile("cp.async.commit_group;" ::: "memory");

        const int buf = it & 3;
        const uint32_t sa = smem_u32(smem + buf * STG_ELEM);
        const uint32_t sb = sa + 8192;
        #pragma unroll
        for (int ks = 0; ks < 2; ks++) {
            uint32_t a[4][4], b[8][2];
            #pragma unroll
            for (int mf = 0; mf < 4; mf++) {
                int row = wm + mf * 16 + (lane & 15);
                int ch  = ks * 2 + (lane >> 4);
                uint32_t addr = sa + row * 64 + ((ch ^ ((row >> 1) & 3)) << 4);
                ldm_x4(a[mf][0], a[mf][1], a[mf][2], a[mf][3], addr);
            }
            #pragma unroll
            for (int bi = 0; bi < 4; bi++) {
                int row = wn + bi * 16 + (lane & 15);
                int ch  = ks * 2 + (lane >> 4);
                uint32_t addr = sb + row * 64 + ((ch ^ ((row >> 1) & 3)) << 4);
                uint32_t r0, r1, r2, r3;
                ldm_x4(r0, r1, r2, r3, addr);
                b[bi*2+0][0] = r0; b[bi*2+0][1] = r2;
                b[bi*2+1][0] = r1; b[bi*2+1][1] = r3;
            }
            #pragma unroll
            for (int mf = 0; mf < 4; mf++)
                #pragma unroll
                for (int nf = 0; nf < 8; nf++)
                    mma_f16(acc[mf][nf], a[mf], b[nf]);
        }
    }

    // ---------------- epilogue ------------------------------------------------
    float bc[8][2];
    #pragma unroll
    for (int nf = 0; nf < 8; nf++) {
        float2 bv = __ldg((const float2*)&bias[n0 + wn + nf * 8 + (lane & 3) * 2]);
        bc[nf][0] = bv.x; bc[nf][1] = bv.y;
    }

    #pragma unroll
    for (int mf = 0; mf < 4; mf++) {
        #pragma unroll
        for (int rh = 0; rh < 2; rh++) {
            const int gr = m0 + wm + mf * 16 + (lane >> 2) + rh * 8;
            if (gr >= M) continue;
            int es = 0, eo = 0;
            if (EPI == 2) { es = edges[2*gr]; eo = edges[2*gr + 1]; }
            #pragma unroll
            for (int nf = 0; nf < 8; nf++) {
                const int col = n0 + wn + nf * 8 + (lane & 3) * 2;
                float v0 = fmaxf(acc[mf][nf][rh*2+0] + bc[nf][0], 0.f);
                float v1 = fmaxf(acc[mf][nf][rh*2+1] + bc[nf][1], 0.f);
                if (EPI == 0) {
                    float2 v = make_float2(v0, v1);
                    *(float2*)&outf[(size_t)gr * ostride + col] = v;
                } else if (EPI == 3) {
                    __half2 v = __halves2half2(__float2half_rn(v0), __float2half_rn(v1));
                    *(__half2*)&outh[(size_t)gr * ostride + col] = v;
                } else if (EPI == 1) {
                    __half h0 = __float2half_rn(v0), h1 = __float2half_rn(v1);
                    __half l0 = __float2half_rn(v0 - __half2float(h0));
                    __half l1 = __float2half_rn(v1 - __half2float(h1));
                    __half* p = outh + (size_t)gr * (2 * K2) + col;
                    *(__half2*)p        = __halves2half2(h0, h1);
                    *(__half2*)(p + K2) = __halves2half2(l0, l1);
                } else {
                    if (col < HID) {
                        red_add2(&pooled[(size_t)es * HID + col], v0, v1);
                    } else if (col < HID + DOUT) {
                        float2 v = make_float2(v0, v1);
                        *(float2*)&newp[(size_t)gr * DOUT + (col - HID)] = v;
                    } else {
                        red_add2(&pooled[(size_t)eo * HID + (col - HID - DOUT)], v0, v1);
                    }
                }
            }
        }
    }
}

// ---------------- launch ------------------------------------------------------
extern "C" void kernel_launch(void* const* d_in, const int* in_sizes, int n_in,
                              void* d_out, int out_size) {
    const float* obj  = (const float*)d_in[0];
    const float* pred = (const float*)d_in[1];
    const int*   edges= (const int*)  d_in[2];
    const float* W1a  = (const float*)d_in[3];
    const float* b1a  = (const float*)d_in[4];
    const float* W1b  = (const float*)d_in[5];
    const float* b1b  = (const float*)d_in[6];
    const float* W2a  = (const float*)d_in[7];
    const float* b2a  = (const float*)d_in[8];
    const float* W2b  = (const float*)d_in[9];
    const float* b2b  = (const float*)d_in[10];

    float* out     = (float*)d_out;
    float* new_obj = out;                       // [O, 128]
    float* new_p   = out + (size_t)O_N * DOUT;  // [T, 128]

    __half *curt, *h16, *p2, *h2, *bt1, *bt2, *bt3, *bt4;
    float *pooled, *cnt;
    cudaGetSymbolAddress((void**)&curt,   g_curt);
    cudaGetSymbolAddress((void**)&h16,    g_h);
    cudaGetSymbolAddress((void**)&pooled, g_pool);
    cudaGetSymbolAddress((void**)&p2,     g_pool2);
    cudaGetSymbolAddress((void**)&h2,     g_h2);
    cudaGetSymbolAddress((void**)&cnt,    g_cnt);
    cudaGetSymbolAddress((void**)&bt1,    g_bt1);
    cudaGetSymbolAddress((void**)&bt2,    g_bt2);
    cudaGetSymbolAddress((void**)&bt3,    g_bt3);
    cudaGetSymbolAddress((void**)&bt4,    g_bt4);

    const int SMEM = STG * STG_ELEM * 2;   // 65536 bytes
    cudaFuncSetAttribute((const void*)mma_gemm<0>, cudaFuncAttributeMaxDynamicSharedMemorySize, SMEM);
    cudaFuncSetAttribute((const void*)mma_gemm<1>, cudaFuncAttributeMaxDynamicSharedMemorySize, SMEM);
    cudaFuncSetAttribute((const void*)mma_gemm<2>, cudaFuncAttributeMaxDynamicSharedMemorySize, SMEM);
    cudaFuncSetAttribute((const void*)mma_gemm<3>, cudaFuncAttributeMaxDynamicSharedMemorySize, SMEM);

    cudaMemsetAsync(pooled, 0, (size_t)O_N * HID * sizeof(float));
    cudaMemsetAsync(cnt,    0, (size_t)O_N * sizeof(float));

    {   size_t n = (size_t)512 * 384;
        wprep1<<<(unsigned)((n + 255) / 256), 256>>>(W1a, bt1, 384, 512); }
    {   size_t n = (size_t)1152 * 512;
        wprep1<<<(unsigned)((n + 255) / 256), 256>>>(W1b, bt2, 512, 1152); }
    {   size_t n = (size_t)512 * 1024;
        wprep2<<<(unsigned)((n + 255) / 256), 256>>>(W2a, bt3, 512, 512); }
    {   size_t n = (size_t)128 * 1024;
        wprep2<<<(unsigned)((n + 255) / 256), 256>>>(W2b, bt4, 512, 128); }

    gather_conv<<<(T_N * 96 + 255) / 256, 256>>>(
        (const float4*)obj, (const float4*)pred, edges, curt);
    counts_kernel<<<(T_N + 255) / 256, 256>>>(edges, cnt);

    const int MT_T = (T_N + 127) / 128;   // 1563
    const int MT_O = (O_N + 127) / 128;   // 391

    // GEMM1 (fp16 1-term, Kc=384): h = relu(curt @ W1a + b1a) -> plain fp16
    mma_gemm<3><<<dim3(4, MT_T), 128, SMEM>>>(
        curt, bt1, b1a, nullptr, h16,
        T_N, 384, 384, HID, 0, nullptr, nullptr, nullptr);

    // GEMM2 (fp16 1-term, Kc=512): scatter s/o + store new_p
    mma_gemm<2><<<dim3(9, MT_T), 128, SMEM>>>(
        h16, bt2, b1b, nullptr, nullptr,
        T_N, 512, 512, 0, 0, edges, pooled, new_p);

    pscale_conv<<<(O_N * (HID / 4) + 255) / 256, 256>>>((const float4*)pooled, cnt, p2);

    // GEMM3 (fp16 2-term, Kc=1024): h2 = relu(pooled @ W2a + b2a) -> fp16 hi/lo
    mma_gemm<1><<<dim3(4, MT_O), 128, SMEM>>>(
        p2, bt3, b2a, nullptr, h2,
        O_N, 1024, 1024, 0, HID, nullptr, nullptr, nullptr);

    // GEMM4 (fp16 2-term): new_obj = relu(h2 @ W2b + b2b)
    mma_gemm<0><<<dim3(1, MT_O), 128, SMEM>>>(
        h2, bt4, b2b, new_obj, nullptr,
        O_N, 1024, 1024, DOUT, 0, nullptr, nullptr, nullptr);
}

// round 7
// speedup vs baseline: 5.7554x; 1.1159x over previous
#include <cuda_runtime.h>
#include <cuda_fp16.h>
#include <cstdint>

#define O_N   50000
#define T_N   200000
#define DIN   128
#define HID   512
#define DOUT  128

// ---------------- device scratch (allocation-free rule) -----------------------
__device__ __half  g_objh [(size_t)O_N * DIN];   // obj  fp16
__device__ __half  g_predh[(size_t)T_N * DIN];   // pred fp16
__device__ __half  g_h    [(size_t)T_N * 512];   // [T, 512] fp16
__device__ float   g_pool [(size_t)O_N * HID];   // fp32 accum
__device__ __half  g_pool16[(size_t)O_N * 512];  // pooled fp16
__device__ __half  g_h2   [(size_t)O_N * 512];   // [O, 512] fp16
__device__ float   g_cnt  [O_N];
__device__ __half  g_bt1[(size_t)512  * 384];    // [N,K] fp16 (W1a^T)
__device__ __half  g_bt2[(size_t)1152 * 512];    // [N,K] fp16 (W1b^T)
__device__ __half  g_bt3[(size_t)512  * 512];    // [N,K] fp16 (W2a^T)
__device__ __half  g_bt4[(size_t)128  * 512];    // [N,K] fp16 (W2b^T)

// ---------------- PTX helpers -------------------------------------------------
__device__ __forceinline__ uint32_t smem_u32(const void* p) {
    uint32_t a;
    asm("{ .reg .u64 t; cvta.to.shared.u64 t, %1; cvt.u32.u64 %0, t; }" : "=r"(a) : "l"(p));
    return a;
}
__device__ __forceinline__ void cp_async16(uint32_t dst, const void* src, int sz) {
    asm volatile("cp.async.cg.shared.global [%0], [%1], 16, %2;"
                 :: "r"(dst), "l"(src), "r"(sz));
}
__device__ __forceinline__ void ldm_x4(uint32_t& r0, uint32_t& r1, uint32_t& r2,
                                       uint32_t& r3, uint32_t addr) {
    asm volatile("ldmatrix.sync.aligned.m8n8.x4.shared.b16 {%0,%1,%2,%3}, [%4];"
                 : "=r"(r0), "=r"(r1), "=r"(r2), "=r"(r3) : "r"(addr));
}
__device__ __forceinline__ void mma_f16(float* c, const uint32_t* a, const uint32_t* b) {
    asm volatile("mma.sync.aligned.m16n8k16.row.col.f32.f16.f16.f32 "
                 "{%0,%1,%2,%3}, {%4,%5,%6,%7}, {%8,%9}, {%0,%1,%2,%3};"
                 : "+f"(c[0]), "+f"(c[1]), "+f"(c[2]), "+f"(c[3])
                 : "r"(a[0]), "r"(a[1]), "r"(a[2]), "r"(a[3]), "r"(b[0]), "r"(b[1]));
}
__device__ __forceinline__ void red_add2(float* p, float a, float b) {
    asm volatile("red.global.add.v2.f32 [%0], {%1,%2};"
                 :: "l"(p), "f"(a), "f"(b) : "memory");
}

// ---------------- feeders -----------------------------------------------------
// fp32 -> fp16 bulk convert (vectorized: 4 floats -> 4 halves per thread)
__global__ void f2h(const float4* __restrict__ src, __half2* __restrict__ dst, int n4) {
    int i = blockIdx.x * 256 + threadIdx.x;
    if (i >= n4) return;
    float4 v = src[i];
    dst[2*i]   = __halves2half2(__float2half_rn(v.x), __float2half_rn(v.y));
    dst[2*i+1] = __halves2half2(__float2half_rn(v.z), __float2half_rn(v.w));
}

// plain fp16 transpose: Bt[n,k] = W[k,n]
__global__ void wprep1(const float* __restrict__ W, __half* __restrict__ Bt,
                       int K, int N) {
    size_t idx = (size_t)blockIdx.x * 256 + threadIdx.x;
    if (idx >= (size_t)N * K) return;
    int n = (int)(idx / K), k = (int)(idx % K);
    Bt[idx] = __float2half_rn(W[(size_t)k * N + n]);
}

__global__ void counts_kernel(const int* __restrict__ edges, float* __restrict__ cnt) {
    int t = blockIdx.x * 256 + threadIdx.x;
    if (t >= T_N) return;
    atomicAdd(&cnt[edges[2*t]], 1.0f);
    atomicAdd(&cnt[edges[2*t + 1]], 1.0f);
}

// pooled/counts -> plain fp16
__global__ void pscale_conv(const float4* __restrict__ pooled, const float* __restrict__ cnt,
                            __half* __restrict__ p16) {
    int i = blockIdx.x * 256 + threadIdx.x;
    if (i >= O_N * (HID / 4)) return;
    int r = i >> 7;
    float c = fminf(fmaxf(cnt[r], 1.0f), 50000.0f);
    float s = 1.0f / c;
    float4 v = pooled[i];
    __half* row = p16 + (size_t)r * 512;
    int c0 = (i & 127) * 4;
    *(__half2*)(row + c0)     = __halves2half2(__float2half_rn(v.x * s), __float2half_rn(v.y * s));
    *(__half2*)(row + c0 + 2) = __halves2half2(__float2half_rn(v.z * s), __float2half_rn(v.w * s));
}

// ---------------- shared GEMM machinery ---------------------------------------
#define BM 128
#define BN 128
#define BK 32
#define STG 4
#define STG_ELEM 8192          // (BM+BN)*BK 2-byte elements per stage

// B-tile loader (shared by both kernels)
__device__ __forceinline__ void ld_tileB(const __half* __restrict__ Bt, uint32_t sb,
                                         int n0, int Kc, int kp, int tid) {
    #pragma unroll
    for (int t = 0; t < 4; t++) {
        int s = tid + t * 128;
        int row = s >> 2, ch = s & 3;
        uint32_t phys = row * 64 + ((ch ^ ((row >> 1) & 3)) << 4);
        cp_async16(sb + phys, Bt + (size_t)(n0 + row) * Kc + kp + ch * 8, 16);
    }
}

// mainloop compute for one buffered chunk
__device__ __forceinline__ void compute_chunk(uint32_t sa, uint32_t sb,
                                              int wm, int wn, int lane,
                                              float acc[4][8][4]) {
    #pragma unroll
    for (int ks = 0; ks < 2; ks++) {
        uint32_t a[4][4], b[8][2];
        #pragma unroll
        for (int mf = 0; mf < 4; mf++) {
            int row = wm + mf * 16 + (lane & 15);
            int ch  = ks * 2 + (lane >> 4);
            uint32_t addr = sa + row * 64 + ((ch ^ ((row >> 1) & 3)) << 4);
            ldm_x4(a[mf][0], a[mf][1], a[mf][2], a[mf][3], addr);
        }
        #pragma unroll
        for (int bi = 0; bi < 4; bi++) {
            int row = wn + bi * 16 + (lane & 15);
            int ch  = ks * 2 + (lane >> 4);
            uint32_t addr = sb + row * 64 + ((ch ^ ((row >> 1) & 3)) << 4);
            uint32_t r0, r1, r2, r3;
            ldm_x4(r0, r1, r2, r3, addr);
            b[bi*2+0][0] = r0; b[bi*2+0][1] = r2;
            b[bi*2+1][0] = r1; b[bi*2+1][1] = r3;
        }
        #pragma unroll
        for (int mf = 0; mf < 4; mf++)
            #pragma unroll
            for (int nf = 0; nf < 8; nf++)
                mma_f16(acc[mf][nf], a[mf], b[nf]);
    }
}

// ---------------- GEMM1 with fused edge gather --------------------------------
// A[r, :] = [objh[s_r] | predh[r] | objh[o_r]]  (K=384), out = relu(A@W1a+b) fp16
__global__ void __launch_bounds__(128, 2)
g1_gemm(const __half* __restrict__ objh, const __half* __restrict__ predh,
        const int* __restrict__ edges, const __half* __restrict__ Bt,
        const float* __restrict__ bias, __half* __restrict__ outh)
{
    extern __shared__ uint16_t smem[];
    const int tid  = threadIdx.x;
    const int wid  = tid >> 5;
    const int lane = tid & 31;
    const int m0   = blockIdx.y * BM;
    const int n0   = blockIdx.x * BN;
    const int wm   = (wid >> 1) * 64;
    const int wn   = (wid & 1) * 64;
    const int M    = T_N;
    const int Kc   = 384;

    // cache edge indices for this thread's 4 A-load rows
    int rs[4], ro[4], rv[4];
    #pragma unroll
    for (int t = 0; t < 4; t++) {
        int row = (tid + t * 128) >> 2;
        int gr  = m0 + row;
        rv[t] = (gr < M);
        rs[t] = rv[t] ? edges[2*gr]     : 0;
        ro[t] = rv[t] ? edges[2*gr + 1] : 0;
    }

    float acc[4][8][4];
    #pragma unroll
    for (int i = 0; i < 4; i++)
        #pragma unroll
        for (int j = 0; j < 8; j++)
            #pragma unroll
            for (int k = 0; k < 4; k++) acc[i][j][k] = 0.f;

    auto ld_tile = [&](int it, int buf) {
        const int kp  = it * BK;
        const int reg = kp >> 7;          // 0: obj[s], 1: pred, 2: obj[o]
        const int kc  = kp & 127;
        uint32_t sa = smem_u32(smem + buf * STG_ELEM);
        uint32_t sb = sa + 8192;
        #pragma unroll
        for (int t = 0; t < 4; t++) {
            int s = tid + t * 128;
            int row = s >> 2, ch = s & 3;
            uint32_t phys = row * 64 + ((ch ^ ((row >> 1) & 3)) << 4);
            int gr = m0 + row;
            int col = kc + ch * 8;
            const __half* src;
            if (reg == 0)      src = objh  + (size_t)rs[t] * DIN + col;
            else if (reg == 1) src = predh + (size_t)(rv[t] ? gr : 0) * DIN + col;
            else               src = objh  + (size_t)ro[t] * DIN + col;
            cp_async16(sa + phys, src, rv[t] ? 16 : 0);
        }
        ld_tileB(Bt, sb, n0, Kc, kp, tid);
    };

    const int NC = Kc / BK;   // 12
    #pragma unroll
    for (int i = 0; i < STG - 1; i++) {
        ld_tile(i, i);
        asm volatile("cp.async.commit_group;" ::: "memory");
    }
    for (int it = 0; it < NC; it++) {
        asm volatile("cp.async.wait_group 2;" ::: "memory");
        __syncthreads();
        if (it + STG - 1 < NC) ld_tile(it + STG - 1, (it + STG - 1) & 3);
        asm volatile("cp.async.commit_group;" ::: "memory");
        const int buf = it & 3;
        uint32_t sa = smem_u32(smem + buf * STG_ELEM);
        compute_chunk(sa, sa + 8192, wm, wn, lane, acc);
    }

    float bc[8][2];
    #pragma unroll
    for (int nf = 0; nf < 8; nf++) {
        float2 bv = __ldg((const float2*)&bias[n0 + wn + nf * 8 + (lane & 3) * 2]);
        bc[nf][0] = bv.x; bc[nf][1] = bv.y;
    }
    #pragma unroll
    for (int mf = 0; mf < 4; mf++)
        #pragma unroll
        for (int rh = 0; rh < 2; rh++) {
            const int gr = m0 + wm + mf * 16 + (lane >> 2) + rh * 8;
            if (gr >= M) continue;
            #pragma unroll
            for (int nf = 0; nf < 8; nf++) {
                const int col = n0 + wn + nf * 8 + (lane & 3) * 2;
                float v0 = fmaxf(acc[mf][nf][rh*2+0] + bc[nf][0], 0.f);
                float v1 = fmaxf(acc[mf][nf][rh*2+1] + bc[nf][1], 0.f);
                *(__half2*)&outh[(size_t)gr * HID + col] =
                    __halves2half2(__float2half_rn(v0), __float2half_rn(v1));
            }
        }
}

// ---------------- generic GEMM -------------------------------------------------
// EPI 0: fp32 store    EPI 2: GEMM2 router    EPI 3: plain fp16 store
template<int EPI>
__global__ void __launch_bounds__(128, 2)
mma_gemm(const __half* __restrict__ A, const __half* __restrict__ Bt,
         const float* __restrict__ bias, float* __restrict__ outf,
         __half* __restrict__ outh,
         int M, int strideA, int Kc, int ostride,
         const int* __restrict__ edges, float* __restrict__ pooled,
         float* __restrict__ newp)
{
    extern __shared__ uint16_t smem[];
    const int tid  = threadIdx.x;
    const int wid  = tid >> 5;
    const int lane = tid & 31;
    const int m0   = blockIdx.y * BM;
    const int n0   = blockIdx.x * BN;
    const int wm   = (wid >> 1) * 64;
    const int wn   = (wid & 1) * 64;

    float acc[4][8][4];
    #pragma unroll
    for (int i = 0; i < 4; i++)
        #pragma unroll
        for (int j = 0; j < 8; j++)
            #pragma unroll
            for (int k = 0; k < 4; k++) acc[i][j][k] = 0.f;

    auto ld_tile = [&](int it, int buf) {
        const int kp = it * BK;
        uint32_t sa = smem_u32(smem + buf * STG_ELEM);
        uint32_t sb = sa + 8192;
        #pragma unroll
        for (int t = 0; t < 4; t++) {
            int s = tid + t * 128;
            int row = s >> 2, ch = s & 3;
            uint32_t phys = row * 64 + ((ch ^ ((row >> 1) & 3)) << 4);
            int gr = m0 + row;
            cp_async16(sa + phys,
                       A + (size_t)(gr < M ? gr : 0) * strideA + kp + ch * 8,
                       gr < M ? 16 : 0);
        }
        ld_tileB(Bt, sb, n0, Kc, kp, tid);
    };

    const int NC = Kc / BK;
    #pragma unroll
    for (int i = 0; i < STG - 1; i++) {
        ld_tile(i, i);
        asm volatile("cp.async.commit_group;" ::: "memory");
    }
    for (int it = 0; it < NC; it++) {
        asm volatile("cp.async.wait_group 2;" ::: "memory");
        __syncthreads();
        if (it + STG - 1 < NC) ld_tile(it + STG - 1, (it + STG - 1) & 3);
        asm volatile("cp.async.commit_group;" ::: "memory");
        const int buf = it & 3;
        uint32_t sa = smem_u32(smem + buf * STG_ELEM);
        compute_chunk(sa, sa + 8192, wm, wn, lane, acc);
    }

    float bc[8][2];
    #pragma unroll
    for (int nf = 0; nf < 8; nf++) {
        float2 bv = __ldg((const float2*)&bias[n0 + wn + nf * 8 + (lane & 3) * 2]);
        bc[nf][0] = bv.x; bc[nf][1] = bv.y;
    }

    #pragma unroll
    for (int mf = 0; mf < 4; mf++)
        #pragma unroll
        for (int rh = 0; rh < 2; rh++) {
            const int gr = m0 + wm + mf * 16 + (lane >> 2) + rh * 8;
            if (gr >= M) continue;
            int es = 0, eo = 0;
            if (EPI == 2) { es = edges[2*gr]; eo = edges[2*gr + 1]; }
            #pragma unroll
            for (int nf = 0; nf < 8; nf++) {
                const int col = n0 + wn + nf * 8 + (lane & 3) * 2;
                float v0 = fmaxf(acc[mf][nf][rh*2+0] + bc[nf][0], 0.f);
                float v1 = fmaxf(acc[mf][nf][rh*2+1] + bc[nf][1], 0.f);
                if (EPI == 0) {
                    *(float2*)&outf[(size_t)gr * ostride + col] = make_float2(v0, v1);
                } else if (EPI == 3) {
                    *(__half2*)&outh[(size_t)gr * ostride + col] =
                        __halves2half2(__float2half_rn(v0), __float2half_rn(v1));
                } else {
                    if (col < HID) {
                        red_add2(&pooled[(size_t)es * HID + col], v0, v1);
                    } else if (col < HID + DOUT) {
                        *(float2*)&newp[(size_t)gr * DOUT + (col - HID)] = make_float2(v0, v1);
                    } else {
                        red_add2(&pooled[(size_t)eo * HID + (col - HID - DOUT)], v0, v1);
                    }
                }
            }
        }
}

// ---------------- launch ------------------------------------------------------
extern "C" void kernel_launch(void* const* d_in, const int* in_sizes, int n_in,
                              void* d_out, int out_size) {
    const float* obj  = (const float*)d_in[0];
    const float* pred = (const float*)d_in[1];
    const int*   edges= (const int*)  d_in[2];
    const float* W1a  = (const float*)d_in[3];
    const float* b1a  = (const float*)d_in[4];
    const float* W1b  = (const float*)d_in[5];
    const float* b1b  = (const float*)d_in[6];
    const float* W2a  = (const float*)d_in[7];
    const float* b2a  = (const float*)d_in[8];
    const float* W2b  = (const float*)d_in[9];
    const float* b2b  = (const float*)d_in[10];

    float* out     = (float*)d_out;
    float* new_obj = out;                       // [O, 128]
    float* new_p   = out + (size_t)O_N * DOUT;  // [T, 128]

    __half *objh, *predh, *h16, *p16, *h2, *bt1, *bt2, *bt3, *bt4;
    float *pooled, *cnt;
    cudaGetSymbolAddress((void**)&objh,   g_objh);
    cudaGetSymbolAddress((void**)&predh,  g_predh);
    cudaGetSymbolAddress((void**)&h16,    g_h);
    cudaGetSymbolAddress((void**)&pooled, g_pool);
    cudaGetSymbolAddress((void**)&p16,    g_pool16);
    cudaGetSymbolAddress((void**)&h2,     g_h2);
    cudaGetSymbolAddress((void**)&cnt,    g_cnt);
    cudaGetSymbolAddress((void**)&bt1,    g_bt1);
    cudaGetSymbolAddress((void**)&bt2,    g_bt2);
    cudaGetSymbolAddress((void**)&bt3,    g_bt3);
    cudaGetSymbolAddress((void**)&bt4,    g_bt4);

    const int SMEM = STG * STG_ELEM * 2;   // 65536 bytes
    cudaFuncSetAttribute((const void*)g1_gemm,     cudaFuncAttributeMaxDynamicSharedMemorySize, SMEM);
    cudaFuncSetAttribute((const void*)mma_gemm<0>, cudaFuncAttributeMaxDynamicSharedMemorySize, SMEM);
    cudaFuncSetAttribute((const void*)mma_gemm<2>, cudaFuncAttributeMaxDynamicSharedMemorySize, SMEM);
    cudaFuncSetAttribute((const void*)mma_gemm<3>, cudaFuncAttributeMaxDynamicSharedMemorySize, SMEM);

    cudaMemsetAsync(pooled, 0, (size_t)O_N * HID * sizeof(float));
    cudaMemsetAsync(cnt,    0, (size_t)O_N * sizeof(float));

    // fp16 conversions of gather sources
    {   int n4 = O_N * DIN / 4;
        f2h<<<(n4 + 255) / 256, 256>>>((const float4*)obj, (__half2*)objh, n4); }
    {   int n4 = T_N * DIN / 4;
        f2h<<<(n4 + 255) / 256, 256>>>((const float4*)pred, (__half2*)predh, n4); }

    // weight transposes (plain fp16)
    {   size_t n = (size_t)512 * 384;
        wprep1<<<(unsigned)((n + 255) / 256), 256>>>(W1a, bt1, 384, 512); }
    {   size_t n = (size_t)1152 * 512;
        wprep1<<<(unsigned)((n + 255) / 256), 256>>>(W1b, bt2, 512, 1152); }
    {   size_t n = (size_t)512 * 512;
        wprep1<<<(unsigned)((n + 255) / 256), 256>>>(W2a, bt3, 512, 512); }
    {   size_t n = (size_t)128 * 512;
        wprep1<<<(unsigned)((n + 255) / 256), 256>>>(W2b, bt4, 512, 128); }

    counts_kernel<<<(T_N + 255) / 256, 256>>>(edges, cnt);

    const int MT_T = (T_N + 127) / 128;   // 1563
    const int MT_O = (O_N + 127) / 128;   // 391

    // GEMM1 (fused gather): h = relu([obj[s]|pred|obj[o]] @ W1a + b1a) -> fp16
    g1_gemm<<<dim3(4, MT_T), 128, SMEM>>>(objh, predh, edges, bt1, b1a, h16);

    // GEMM2: scatter s/o + store new_p
    mma_gemm<2><<<dim3(9, MT_T), 128, SMEM>>>(
        h16, bt2, b1b, nullptr, nullptr,
        T_N, 512, 512, 0, edges, pooled, new_p);

    pscale_conv<<<(O_N * (HID / 4) + 255) / 256, 256>>>((const float4*)pooled, cnt, p16);

    // GEMM3: h2 = relu(pooled @ W2a + b2a) -> fp16
    mma_gemm<3><<<dim3(4, MT_O), 128, SMEM>>>(
        p16, bt3, b2a, nullptr, h2,
        O_N, 512, 512, HID, nullptr, nullptr, nullptr);

    // GEMM4: new_obj = relu(h2 @ W2b + b2b)
    mma_gemm<0><<<dim3(1, MT_O), 128, SMEM>>>(
        h2, bt4, b2b, new_obj, nullptr,
        O_N, 512, 512, DOUT, nullptr, nullptr, nullptr);
}

// round 8
// speedup vs baseline: 5.7967x; 1.0072x over previous
#include <cuda_runtime.h>
#include <cuda_fp16.h>
#include <cstdint>

#define O_N   50000
#define T_N   200000
#define DIN   128
#define HID   512
#define DOUT  128

// ---------------- device scratch (allocation-free rule) -----------------------
__device__ __half  g_objh [(size_t)O_N * DIN];   // obj  fp16
__device__ __half  g_predh[(size_t)T_N * DIN];   // pred fp16
__device__ __half  g_h    [(size_t)T_N * 512];   // [T, 512] fp16
__device__ float   g_pool [(size_t)O_N * HID];   // fp32 accum
__device__ __half  g_pool16[(size_t)O_N * 512];  // pooled fp16
__device__ __half  g_h2   [(size_t)O_N * 512];   // [O, 512] fp16
__device__ float   g_cnt  [O_N];
__device__ __half  g_bt1[(size_t)512  * 384];    // [N,K] fp16 (W1a^T)
__device__ __half  g_bt2[(size_t)1152 * 512];    // [N,K] fp16 (W1b^T)
__device__ __half  g_bt3[(size_t)512  * 512];    // [N,K] fp16 (W2a^T)
__device__ __half  g_bt4[(size_t)128  * 512];    // [N,K] fp16 (W2b^T)

// ---------------- PTX helpers -------------------------------------------------
__device__ __forceinline__ uint32_t smem_u32(const void* p) {
    uint32_t a;
    asm("{ .reg .u64 t; cvta.to.shared.u64 t, %1; cvt.u32.u64 %0, t; }" : "=r"(a) : "l"(p));
    return a;
}
__device__ __forceinline__ void cp_async16(uint32_t dst, const void* src, int sz) {
    asm volatile("cp.async.cg.shared.global [%0], [%1], 16, %2;"
                 :: "r"(dst), "l"(src), "r"(sz));
}
__device__ __forceinline__ void ldm_x4(uint32_t& r0, uint32_t& r1, uint32_t& r2,
                                       uint32_t& r3, uint32_t addr) {
    asm volatile("ldmatrix.sync.aligned.m8n8.x4.shared.b16 {%0,%1,%2,%3}, [%4];"
                 : "=r"(r0), "=r"(r1), "=r"(r2), "=r"(r3) : "r"(addr));
}
__device__ __forceinline__ void mma_f16(float* c, const uint32_t* a, const uint32_t* b) {
    asm volatile("mma.sync.aligned.m16n8k16.row.col.f32.f16.f16.f32 "
                 "{%0,%1,%2,%3}, {%4,%5,%6,%7}, {%8,%9}, {%0,%1,%2,%3};"
                 : "+f"(c[0]), "+f"(c[1]), "+f"(c[2]), "+f"(c[3])
                 : "r"(a[0]), "r"(a[1]), "r"(a[2]), "r"(a[3]), "r"(b[0]), "r"(b[1]));
}
__device__ __forceinline__ void red_add2(float* p, float a, float b) {
    asm volatile("red.global.add.v2.f32 [%0], {%1,%2};"
                 :: "l"(p), "f"(a), "f"(b) : "memory");
}

// ---------------- feeders -----------------------------------------------------
// obj fp32->fp16 convert, fused with zeroing of pooled + cnt.
// grid covers max(pooled float4 count, obj float4 count).
__global__ void f2h_obj_zero(const float4* __restrict__ src, __half2* __restrict__ dst,
                             int n4_obj, float4* __restrict__ pool4, int n4_pool,
                             float* __restrict__ cnt) {
    int i = blockIdx.x * 256 + threadIdx.x;
    if (i < n4_pool) pool4[i] = make_float4(0.f, 0.f, 0.f, 0.f);
    if (i < O_N) cnt[i] = 0.f;
    if (i < n4_obj) {
        float4 v = src[i];
        dst[2*i]   = __halves2half2(__float2half_rn(v.x), __float2half_rn(v.y));
        dst[2*i+1] = __halves2half2(__float2half_rn(v.z), __float2half_rn(v.w));
    }
}

__global__ void f2h(const float4* __restrict__ src, __half2* __restrict__ dst, int n4) {
    int i = blockIdx.x * 256 + threadIdx.x;
    if (i >= n4) return;
    float4 v = src[i];
    dst[2*i]   = __halves2half2(__float2half_rn(v.x), __float2half_rn(v.y));
    dst[2*i+1] = __halves2half2(__float2half_rn(v.z), __float2half_rn(v.w));
}

// plain fp16 transpose: Bt[n,k] = W[k,n]
__global__ void wprep1(const float* __restrict__ W, __half* __restrict__ Bt,
                       int K, int N) {
    size_t idx = (size_t)blockIdx.x * 256 + threadIdx.x;
    if (idx >= (size_t)N * K) return;
    int n = (int)(idx / K), k = (int)(idx % K);
    Bt[idx] = __float2half_rn(W[(size_t)k * N + n]);
}

__global__ void counts_kernel(const int* __restrict__ edges, float* __restrict__ cnt) {
    int t = blockIdx.x * 256 + threadIdx.x;
    if (t >= T_N) return;
    atomicAdd(&cnt[edges[2*t]], 1.0f);
    atomicAdd(&cnt[edges[2*t + 1]], 1.0f);
}

// pooled/counts -> plain fp16
__global__ void pscale_conv(const float4* __restrict__ pooled, const float* __restrict__ cnt,
                            __half* __restrict__ p16) {
    int i = blockIdx.x * 256 + threadIdx.x;
    if (i >= O_N * (HID / 4)) return;
    int r = i >> 7;
    float c = fminf(fmaxf(cnt[r], 1.0f), 50000.0f);
    float s = 1.0f / c;
    float4 v = pooled[i];
    __half* row = p16 + (size_t)r * 512;
    int c0 = (i & 127) * 4;
    *(__half2*)(row + c0)     = __halves2half2(__float2half_rn(v.x * s), __float2half_rn(v.y * s));
    *(__half2*)(row + c0 + 2) = __halves2half2(__float2half_rn(v.z * s), __float2half_rn(v.w * s));
}

// ---------------- shared GEMM machinery ---------------------------------------
#define BM 128
#define BN 128
#define BK 32
#define STG 3
#define STG_ELEM 8192          // (BM+BN)*BK 2-byte elements per stage

__device__ __forceinline__ void ld_tileB(const __half* __restrict__ Bt, uint32_t sb,
                                         int n0, int Kc, int kp, int tid) {
    #pragma unroll
    for (int t = 0; t < 4; t++) {
        int s = tid + t * 128;
        int row = s >> 2, ch = s & 3;
        uint32_t phys = row * 64 + ((ch ^ ((row >> 1) & 3)) << 4);
        cp_async16(sb + phys, Bt + (size_t)(n0 + row) * Kc + kp + ch * 8, 16);
    }
}

__device__ __forceinline__ void compute_chunk(uint32_t sa, uint32_t sb,
                                              int wm, int wn, int lane,
                                              float acc[4][8][4]) {
    #pragma unroll
    for (int ks = 0; ks < 2; ks++) {
        uint32_t a[4][4], b[8][2];
        #pragma unroll
        for (int mf = 0; mf < 4; mf++) {
            int row = wm + mf * 16 + (lane & 15);
            int ch  = ks * 2 + (lane >> 4);
            uint32_t addr = sa + row * 64 + ((ch ^ ((row >> 1) & 3)) << 4);
            ldm_x4(a[mf][0], a[mf][1], a[mf][2], a[mf][3], addr);
        }
        #pragma unroll
        for (int bi = 0; bi < 4; bi++) {
            int row = wn + bi * 16 + (lane & 15);
            int ch  = ks * 2 + (lane >> 4);
            uint32_t addr = sb + row * 64 + ((ch ^ ((row >> 1) & 3)) << 4);
            uint32_t r0, r1, r2, r3;
            ldm_x4(r0, r1, r2, r3, addr);
            b[bi*2+0][0] = r0; b[bi*2+0][1] = r2;
            b[bi*2+1][0] = r1; b[bi*2+1][1] = r3;
        }
        #pragma unroll
        for (int mf = 0; mf < 4; mf++)
            #pragma unroll
            for (int nf = 0; nf < 8; nf++)
                mma_f16(acc[mf][nf], a[mf], b[nf]);
    }
}

// ---------------- GEMM1 with fused edge gather --------------------------------
__global__ void __launch_bounds__(128, 3)
g1_gemm(const __half* __restrict__ objh, const __half* __restrict__ predh,
        const int* __restrict__ edges, const __half* __restrict__ Bt,
        const float* __restrict__ bias, __half* __restrict__ outh)
{
    extern __shared__ uint16_t smem[];
    const int tid  = threadIdx.x;
    const int wid  = tid >> 5;
    const int lane = tid & 31;
    const int m0   = blockIdx.y * BM;
    const int n0   = blockIdx.x * BN;
    const int wm   = (wid >> 1) * 64;
    const int wn   = (wid & 1) * 64;
    const int M    = T_N;
    const int Kc   = 384;

    int rs[4], ro[4], rv[4];
    #pragma unroll
    for (int t = 0; t < 4; t++) {
        int row = (tid + t * 128) >> 2;
        int gr  = m0 + row;
        rv[t] = (gr < M);
        rs[t] = rv[t] ? edges[2*gr]     : 0;
        ro[t] = rv[t] ? edges[2*gr + 1] : 0;
    }

    float acc[4][8][4];
    #pragma unroll
    for (int i = 0; i < 4; i++)
        #pragma unroll
        for (int j = 0; j < 8; j++)
            #pragma unroll
            for (int k = 0; k < 4; k++) acc[i][j][k] = 0.f;

    auto ld_tile = [&](int it, int buf) {
        const int kp  = it * BK;
        const int reg = kp >> 7;
        const int kc  = kp & 127;
        uint32_t sa = smem_u32(smem + buf * STG_ELEM);
        uint32_t sb = sa + 8192;
        #pragma unroll
        for (int t = 0; t < 4; t++) {
            int s = tid + t * 128;
            int row = s >> 2, ch = s & 3;
            uint32_t phys = row * 64 + ((ch ^ ((row >> 1) & 3)) << 4);
            int gr = m0 + row;
            int col = kc + ch * 8;
            const __half* src;
            if (reg == 0)      src = objh  + (size_t)rs[t] * DIN + col;
            else if (reg == 1) src = predh + (size_t)(rv[t] ? gr : 0) * DIN + col;
            else               src = objh  + (size_t)ro[t] * DIN + col;
            cp_async16(sa + phys, src, rv[t] ? 16 : 0);
        }
        ld_tileB(Bt, sb, n0, Kc, kp, tid);
    };

    const int NC = Kc / BK;   // 12
    #pragma unroll
    for (int i = 0; i < STG - 1; i++) {
        ld_tile(i, i);
        asm volatile("cp.async.commit_group;" ::: "memory");
    }
    for (int it = 0; it < NC; it++) {
        asm volatile("cp.async.wait_group 1;" ::: "memory");
        __syncthreads();
        if (it + STG - 1 < NC) ld_tile(it + STG - 1, (it + STG - 1) % STG);
        asm volatile("cp.async.commit_group;" ::: "memory");
        const int buf = it % STG;
        uint32_t sa = smem_u32(smem + buf * STG_ELEM);
        compute_chunk(sa, sa + 8192, wm, wn, lane, acc);
    }

    float bc[8][2];
    #pragma unroll
    for (int nf = 0; nf < 8; nf++) {
        float2 bv = __ldg((const float2*)&bias[n0 + wn + nf * 8 + (lane & 3) * 2]);
        bc[nf][0] = bv.x; bc[nf][1] = bv.y;
    }
    #pragma unroll
    for (int mf = 0; mf < 4; mf++)
        #pragma unroll
        for (int rh = 0; rh < 2; rh++) {
            const int gr = m0 + wm + mf * 16 + (lane >> 2) + rh * 8;
            if (gr >= M) continue;
            #pragma unroll
            for (int nf = 0; nf < 8; nf++) {
                const int col = n0 + wn + nf * 8 + (lane & 3) * 2;
                float v0 = fmaxf(acc[mf][nf][rh*2+0] + bc[nf][0], 0.f);
                float v1 = fmaxf(acc[mf][nf][rh*2+1] + bc[nf][1], 0.f);
                *(__half2*)&outh[(size_t)gr * HID + col] =
                    __halves2half2(__float2half_rn(v0), __float2half_rn(v1));
            }
        }
}

// ---------------- generic GEMM -------------------------------------------------
// EPI 0: fp32 store    EPI 2: GEMM2 router    EPI 3: plain fp16 store
template<int EPI>
__global__ void __launch_bounds__(128, 3)
mma_gemm(const __half* __restrict__ A, const __half* __restrict__ Bt,
         const float* __restrict__ bias, float* __restrict__ outf,
         __half* __restrict__ outh,
         int M, int strideA, int Kc, int ostride,
         const int* __restrict__ edges, float* __restrict__ pooled,
         float* __restrict__ newp)
{
    extern __shared__ uint16_t smem[];
    const int tid  = threadIdx.x;
    const int wid  = tid >> 5;
    const int lane = tid & 31;
    const int m0   = blockIdx.y * BM;
    const int n0   = blockIdx.x * BN;
    const int wm   = (wid >> 1) * 64;
    const int wn   = (wid & 1) * 64;

    float acc[4][8][4];
    #pragma unroll
    for (int i = 0; i < 4; i++)
        #pragma unroll
        for (int j = 0; j < 8; j++)
            #pragma unroll
            for (int k = 0; k < 4; k++) acc[i][j][k] = 0.f;

    auto ld_tile = [&](int it, int buf) {
        const int kp = it * BK;
        uint32_t sa = smem_u32(smem + buf * STG_ELEM);
        uint32_t sb = sa + 8192;
        #pragma unroll
        for (int t = 0; t < 4; t++) {
            int s = tid + t * 128;
            int row = s >> 2, ch = s & 3;
            uint32_t phys = row * 64 + ((ch ^ ((row >> 1) & 3)) << 4);
            int gr = m0 + row;
            cp_async16(sa + phys,
                       A + (size_t)(gr < M ? gr : 0) * strideA + kp + ch * 8,
                       gr < M ? 16 : 0);
        }
        ld_tileB(Bt, sb, n0, Kc, kp, tid);
    };

    const int NC = Kc / BK;
    #pragma unroll
    for (int i = 0; i < STG - 1; i++) {
        ld_tile(i, i);
        asm volatile("cp.async.commit_group;" ::: "memory");
    }
    for (int it = 0; it < NC; it++) {
        asm volatile("cp.async.wait_group 1;" ::: "memory");
        __syncthreads();
        if (it + STG - 1 < NC) ld_tile(it + STG - 1, (it + STG - 1) % STG);
        asm volatile("cp.async.commit_group;" ::: "memory");
        const int buf = it % STG;
        uint32_t sa = smem_u32(smem + buf * STG_ELEM);
        compute_chunk(sa, sa + 8192, wm, wn, lane, acc);
    }

    float bc[8][2];
    #pragma unroll
    for (int nf = 0; nf < 8; nf++) {
        float2 bv = __ldg((const float2*)&bias[n0 + wn + nf * 8 + (lane & 3) * 2]);
        bc[nf][0] = bv.x; bc[nf][1] = bv.y;
    }

    #pragma unroll
    for (int mf = 0; mf < 4; mf++)
        #pragma unroll
        for (int rh = 0; rh < 2; rh++) {
            const int gr = m0 + wm + mf * 16 + (lane >> 2) + rh * 8;
            if (gr >= M) continue;
            int es = 0, eo = 0;
            if (EPI == 2) { es = edges[2*gr]; eo = edges[2*gr + 1]; }
            #pragma unroll
            for (int nf = 0; nf < 8; nf++) {
                const int col = n0 + wn + nf * 8 + (lane & 3) * 2;
                float v0 = fmaxf(acc[mf][nf][rh*2+0] + bc[nf][0], 0.f);
                float v1 = fmaxf(acc[mf][nf][rh*2+1] + bc[nf][1], 0.f);
                if (EPI == 0) {
                    *(float2*)&outf[(size_t)gr * ostride + col] = make_float2(v0, v1);
                } else if (EPI == 3) {
                    *(__half2*)&outh[(size_t)gr * ostride + col] =
                        __halves2half2(__float2half_rn(v0), __float2half_rn(v1));
                } else {
                    if (col < HID) {
                        red_add2(&pooled[(size_t)es * HID + col], v0, v1);
                    } else if (col < HID + DOUT) {
                        *(float2*)&newp[(size_t)gr * DOUT + (col - HID)] = make_float2(v0, v1);
                    } else {
                        red_add2(&pooled[(size_t)eo * HID + (col - HID - DOUT)], v0, v1);
                    }
                }
            }
        }
}

// ---------------- launch ------------------------------------------------------
// Launch order is deliberate: ncu capture is -s 5 -c 1 (the 6th launch), which
// must be GEMM2 (mma_gemm<2>) — the dominant kernel.
extern "C" void kernel_launch(void* const* d_in, const int* in_sizes, int n_in,
                              void* d_out, int out_size) {
    const float* obj  = (const float*)d_in[0];
    const float* pred = (const float*)d_in[1];
    const int*   edges= (const int*)  d_in[2];
    const float* W1a  = (const float*)d_in[3];
    const float* b1a  = (const float*)d_in[4];
    const float* W1b  = (const float*)d_in[5];
    const float* b1b  = (const float*)d_in[6];
    const float* W2a  = (const float*)d_in[7];
    const float* b2a  = (const float*)d_in[8];
    const float* W2b  = (const float*)d_in[9];
    const float* b2b  = (const float*)d_in[10];

    float* out     = (float*)d_out;
    float* new_obj = out;                       // [O, 128]
    float* new_p   = out + (size_t)O_N * DOUT;  // [T, 128]

    __half *objh, *predh, *h16, *p16, *h2, *bt1, *bt2, *bt3, *bt4;
    float *pooled, *cnt;
    cudaGetSymbolAddress((void**)&objh,   g_objh);
    cudaGetSymbolAddress((void**)&predh,  g_predh);
    cudaGetSymbolAddress((void**)&h16,    g_h);
    cudaGetSymbolAddress((void**)&pooled, g_pool);
    cudaGetSymbolAddress((void**)&p16,    g_pool16);
    cudaGetSymbolAddress((void**)&h2,     g_h2);
    cudaGetSymbolAddress((void**)&cnt,    g_cnt);
    cudaGetSymbolAddress((void**)&bt1,    g_bt1);
    cudaGetSymbolAddress((void**)&bt2,    g_bt2);
    cudaGetSymbolAddress((void**)&bt3,    g_bt3);
    cudaGetSymbolAddress((void**)&bt4,    g_bt4);

    const int SMEM = STG * STG_ELEM * 2;   // 49152 bytes
    cudaFuncSetAttribute((const void*)g1_gemm,     cudaFuncAttributeMaxDynamicSharedMemorySize, SMEM);
    cudaFuncSetAttribute((const void*)mma_gemm<0>, cudaFuncAttributeMaxDynamicSharedMemorySize, SMEM);
    cudaFuncSetAttribute((const void*)mma_gemm<2>, cudaFuncAttributeMaxDynamicSharedMemorySize, SMEM);
    cudaFuncSetAttribute((const void*)mma_gemm<3>, cudaFuncAttributeMaxDynamicSharedMemorySize, SMEM);

    const int MT_T = (T_N + 127) / 128;   // 1563
    const int MT_O = (O_N + 127) / 128;   // 391

    // 1: obj fp16 convert + zero pooled/cnt (single kernel, covers pooled span)
    {   int n4_obj  = O_N * DIN / 4;            // 1.6M
        int n4_pool = O_N * HID / 4;            // 6.4M
        f2h_obj_zero<<<(n4_pool + 255) / 256, 256>>>(
            (const float4*)obj, (__half2*)objh, n4_obj,
            (float4*)pooled, n4_pool, cnt); }

    // 2: pred fp16 convert
    {   int n4 = T_N * DIN / 4;
        f2h<<<(n4 + 255) / 256, 256>>>((const float4*)pred, (__half2*)predh, n4); }

    // 3: W1a^T
    {   size_t n = (size_t)512 * 384;
        wprep1<<<(unsigned)((n + 255) / 256), 256>>>(W1a, bt1, 384, 512); }

    // 4: W1b^T
    {   size_t n = (size_t)1152 * 512;
        wprep1<<<(unsigned)((n + 255) / 256), 256>>>(W1b, bt2, 512, 1152); }

    // 5: GEMM1 (fused gather)
    g1_gemm<<<dim3(4, MT_T), 128, SMEM>>>(objh, predh, edges, bt1, b1a, h16);

    // 6: GEMM2 (scatter s/o + new_p)  <-- ncu captures this launch
    mma_gemm<2><<<dim3(9, MT_T), 128, SMEM>>>(
        h16, bt2, b1b, nullptr, nullptr,
        T_N, 512, 512, 0, edges, pooled, new_p);

    // 7: counts
    counts_kernel<<<(T_N + 255) / 256, 256>>>(edges, cnt);

    // 8-9: W2a^T, W2b^T
    {   size_t n = (size_t)512 * 512;
        wprep1<<<(unsigned)((n + 255) / 256), 256>>>(W2a, bt3, 512, 512); }
    {   size_t n = (size_t)128 * 512;
        wprep1<<<(unsigned)((n + 255) / 256), 256>>>(W2b, bt4, 512, 128); }

    // 10: pooled scale + fp16
    pscale_conv<<<(O_N * (HID / 4) + 255) / 256, 256>>>((const float4*)pooled, cnt, p16);

    // 11: GEMM3
    mma_gemm<3><<<dim3(4, MT_O), 128, SMEM>>>(
        p16, bt3, b2a, nullptr, h2,
        O_N, 512, 512, HID, nullptr, nullptr, nullptr);

    // 12: GEMM4
    mma_gemm<0><<<dim3(1, MT_O), 128, SMEM>>>(
        h2, bt4, b2b, new_obj, nullptr,
        O_N, 512, 512, DOUT, nullptr, nullptr, nullptr);
}